// round 12
// baseline (speedup 1.0000x reference)
#include <cuda_runtime.h>
#include <cuda_bf16.h>
#include <math.h>
#include <stdint.h>

#define NEGV (-1e10f)
#define KSPAN 1024
#define KANT 50
#define GIDIM 512
#define HID 1000
#define MROWS (KSPAN*KANT)   // 51200
#define KPA 1088             // MLP K: [gj(512) | gi*gj(512) | onehot(18) pad 64]
#define NPAD 1024
#define NSLOTS 16
#define MLP_SMEM 84672

// ---------------- device scratch ----------------
__device__ float d_proj[KSPAN*GIDIM];
__device__ float d_ant[KSPAN*KSPAN];
__device__ float d_bs[KSPAN*KANT];
__device__ int   d_bi[KSPAN*KANT];
__device__ __nv_bfloat16 d_A2[(size_t)MROWS*KPA];
__device__ __nv_bfloat16 d_B2t[(size_t)NPAD*KPA];    // [W1b | W1c | Vc rows | 0pad] bf16
__device__ float d_B1tf[(size_t)NPAD*GIDIM];         // W1a^T fp32
__device__ float d_WfTf[(size_t)GIDIM*1024];         // Wf^T fp32 [512][1024]
__device__ float d_Vi[(size_t)KSPAN*NPAD];
__device__ float d_Vg[8*NPAD];
__device__ float d_w2p[NPAD];
__device__ float d_b1p[NPAD];
__device__ float d_part[(size_t)NSLOTS*MROWS];
__device__ float d_sa[MROWS];
__device__ float d_an[KSPAN*GIDIM];
__device__ float d_gnext[KSPAN*GIDIM];

// ---------------- helpers ----------------
__device__ __forceinline__ uint32_t smem_u32(const void* p){
    uint32_t a; asm("{ .reg .u64 t; cvta.to.shared.u64 t, %1; cvt.u32.u64 %0, t; }" : "=r"(a) : "l"(p));
    return a;
}
__device__ __forceinline__ void cpasync16(uint32_t dst, const void* src){
    asm volatile("cp.async.cg.shared.global [%0], [%1], 16;\n" :: "r"(dst), "l"(src) : "memory");
}
#define WG(n) asm volatile("cp.async.wait_group %0;\n" :: "n"(n) : "memory")
#define CommitG() asm volatile("cp.async.commit_group;\n" ::: "memory")

// ---------------- merged prep ----------------
__global__ void prep_master(const float* __restrict__ W1, const float* __restrict__ Wf,
                            const float* __restrict__ b1, const float* __restrict__ W2,
                            const float* __restrict__ dist_e, const float* __restrict__ genre_e,
                            const float* __restrict__ spk_e){
    int b = blockIdx.x, t = threadIdx.x;
    if (b < 2048){
        int idx = b*256 + t;                 // over NPAD*512
        int n = idx >> 9, k = idx & 511;
        float a=0.f, bb=0.f, c=0.f;
        if (n < HID){
            a  = W1[(size_t)k*HID + n];
            bb = W1[(size_t)(512+k)*HID + n];
            c  = W1[(size_t)(1024+k)*HID + n];
        }
        d_B1tf[(size_t)n*GIDIM + k] = a;
        d_B2t[(size_t)n*KPA + k]       = __float2bfloat16(bb);
        d_B2t[(size_t)n*KPA + 512 + k] = __float2bfloat16(c);
    } else if (b < 2304){
        int idx = (b-2048)*256 + t;          // over NPAD*64
        int n = idx >> 6, c = idx & 63;
        float s = 0.f;
        if (c < 18 && n < HID){
            int bin = c>>1, lab = (c&1)+1;
            for (int k=0;k<20;k++) s += dist_e[bin*20+k]*W1[(size_t)(1536+k)*HID+n]
                                      + spk_e[lab*20+k]*W1[(size_t)(1576+k)*HID+n];
        }
        d_B2t[(size_t)n*KPA + 1024 + c] = __float2bfloat16(s);
    } else if (b < 4352){
        int idx = (b-2304)*256 + t;          // over 512*1024
        int n = idx >> 10, k = idx & 1023;
        d_WfTf[idx] = Wf[(size_t)k*GIDIM + n];
    } else if (b < 4356){
        int n = (b-4352)*256 + t;
        d_w2p[n] = (n<HID)? W2[n]:0.f; d_b1p[n] = (n<HID)? b1[n]:0.f;
    } else {
        int idx = (b-4356)*256 + t;          // over 8*1024
        int row = idx >> 10, n = idx & 1023;
        float s = 0.f;
        if (n < HID)
            for (int k=0;k<20;k++) s += genre_e[row*20+k]*W1[(size_t)(1556+k)*HID+n];
        d_Vg[row*NPAD+n] = s;
    }
}

// ---------------- fp32 SIMT GEMM 64x64 (r1-proven) ----------------
// mode0: proj=A@B^T (B=coarseW)           -> d_proj
// mode1: ant = acc + s[m]+s[n] + mask     (A=d_proj, B=g)
// mode2: Vi  = acc + b1[n] + Vg[gid[m]]   (A=g, B=d_B1tf)
// mode3: gate: A-rows=[g|an]; f=sig(+bf[n]); d_gnext  (B=d_WfTf, K=1024)
// mode6: fused proj(bx<8, B=coarseW) + Vi(bx>=8, B=d_B1tf), K=512
__global__ void gemm_f32(int mode, const float* __restrict__ A,
                         const float* __restrict__ B, int Kdim,
                         const float* __restrict__ aux0, const float* __restrict__ aux1,
                         const int* __restrict__ auxi){
    __shared__ float As[64][17];
    __shared__ float Bs[64][17];
    int bx = blockIdx.x;
    const float* Bp = B;
    bool m6proj = false;
    int n0;
    if (mode == 6){
        m6proj = (bx < 8);
        Bp = m6proj ? B : d_B1tf;
        n0 = (m6proj ? bx : bx-8)*64;
    } else n0 = bx*64;
    int m0 = blockIdx.y*64;
    int tid = threadIdx.x;
    int tx = tid & 15, ty = tid >> 4;
    float acc[4][4];
    #pragma unroll
    for (int i=0;i<4;i++)
        #pragma unroll
        for (int j=0;j<4;j++) acc[i][j]=0.f;

    for (int k0 = 0; k0 < Kdim; k0 += 16){
        #pragma unroll
        for (int it=0; it<4; it++){
            int e = tid + it*256;
            int r = e >> 4, kk = e & 15;
            int gk = k0 + kk;
            float av, bv;
            int gm = m0 + r, gn = n0 + r;
            if (mode == 3)
                av = (gk < GIDIM) ? A[(size_t)gm*GIDIM + gk] : aux1[(size_t)gm*GIDIM + gk - GIDIM];
            else
                av = A[(size_t)gm*Kdim + gk];
            bv = Bp[(size_t)gn*Kdim + gk];
            As[r][kk] = av;
            Bs[r][kk] = bv;
        }
        __syncthreads();
        #pragma unroll
        for (int kk=0; kk<16; kk++){
            float a4[4], b4[4];
            #pragma unroll
            for (int i=0;i<4;i++) a4[i] = As[ty*4+i][kk];
            #pragma unroll
            for (int j=0;j<4;j++) b4[j] = Bs[tx*4+j][kk];
            #pragma unroll
            for (int i=0;i<4;i++)
                #pragma unroll
                for (int j=0;j<4;j++) acc[i][j] += a4[i]*b4[j];
        }
        __syncthreads();
    }
    #pragma unroll
    for (int i=0;i<4;i++){
        int m = m0 + ty*4 + i;
        #pragma unroll
        for (int j=0;j<4;j++){
            int n = n0 + tx*4 + j;
            float v = acc[i][j];
            if (mode==0 || (mode==6 && m6proj)){
                d_proj[(size_t)m*GIDIM + n] = v;
            } else if (mode==1){
                v += aux0[m] + aux0[n];
                if (n >= m) v += NEGV;
                d_ant[(size_t)m*KSPAN + n] = v;
            } else if (mode==2 || mode==6){
                d_Vi[(size_t)m*NPAD + n] = v + d_b1p[n] + d_Vg[auxi[m]*NPAD + n];
            } else {
                float f = 1.f/(1.f + expf(-(v + aux0[n])));
                float gv = A[(size_t)m*GIDIM + n];
                float av2 = aux1[(size_t)m*GIDIM + n];
                d_gnext[(size_t)m*GIDIM + n] = (m == 0) ? gv : f*gv + (1.f-f)*av2;
            }
        }
    }
}

// ---------------- top-K bitonic ----------------
__global__ void topk_kernel(){
    int row = blockIdx.x;
    __shared__ unsigned long long sk[1024];
    for (int j=threadIdx.x; j<1024; j+=512){
        unsigned int b = __float_as_uint(d_ant[(size_t)row*KSPAN+j]);
        unsigned int asc = (b & 0x80000000u) ? ~b : (b | 0x80000000u);
        sk[j] = (((unsigned long long)(~asc))<<32) | (unsigned int)j;
    }
    __syncthreads();
    for (int k=2;k<=1024;k<<=1)
        for (int j=k>>1;j>0;j>>=1){
            for (int i=threadIdx.x;i<1024;i+=512){
                int ixj = i^j;
                if (ixj>i){
                    bool up = ((i&k)==0);
                    unsigned long long a=sk[i], b=sk[ixj];
                    if ((a>b)==up){ sk[i]=b; sk[ixj]=a; }
                }
            }
            __syncthreads();
        }
    if (threadIdx.x < KANT){
        int j = (int)(sk[threadIdx.x] & 0xffffffffu);
        d_bi[row*KANT+threadIdx.x] = j;
        d_bs[row*KANT+threadIdx.x] = d_ant[(size_t)row*KSPAN+j];
    }
}

// ---------------- build A2 = [gj | gi*gj | onehot18 | 0pad] from fp32 g ----------------
__global__ void build_A(const float* __restrict__ g, const int* __restrict__ starts,
                        const int* __restrict__ ends, const int* __restrict__ sids){
    int warp = threadIdx.x>>5, lane = threadIdx.x&31;
    int r = blockIdx.x*8 + warp;
    int i = r/KANT, j = d_bi[r];
    const float2* gi2 = (const float2*)(g + (size_t)i*GIDIM);
    const float2* gj2 = (const float2*)(g + (size_t)j*GIDIM);
    unsigned int gjw[8], prw[8];
    #pragma unroll
    for (int w=0; w<8; w++){
        float2 a = gi2[lane*8+w];
        float2 b = gj2[lane*8+w];
        __nv_bfloat162 vb = __floats2bfloat162_rn(b.x, b.y);
        __nv_bfloat162 vp = __floats2bfloat162_rn(a.x*b.x, a.y*b.y);
        gjw[w] = *(unsigned int*)&vb;
        prw[w] = *(unsigned int*)&vp;
    }
    __nv_bfloat16* Ar = d_A2 + (size_t)r*KPA;
    ((uint4*)Ar)[lane*2]   = make_uint4(gjw[0],gjw[1],gjw[2],gjw[3]);
    ((uint4*)Ar)[lane*2+1] = make_uint4(gjw[4],gjw[5],gjw[6],gjw[7]);
    ((uint4*)(Ar+512))[lane*2]   = make_uint4(prw[0],prw[1],prw[2],prw[3]);
    ((uint4*)(Ar+512))[lane*2+1] = make_uint4(prw[4],prw[5],prw[6],prw[7]);
    if (lane < 8){
        int d = ends[i]-starts[j];
        int bin = (d>1)+(d>2)+(d>3)+(d>4)+(d>8)+(d>16)+(d>32)+(d>64);
        int lab = (sids[i]==sids[j]) ? 1 : 2;
        int meta = bin*2 + lab - 1;        // 0..17
        uint4 z = make_uint4(0,0,0,0);
        int dd = meta - lane*8;
        if (dd >= 0 && dd < 8){
            unsigned int val = 0x3F80u << (16*(dd&1));
            ((unsigned int*)&z)[dd>>1] = val;
        }
        ((uint4*)(Ar+1024))[lane] = z;
    }
}

// ---------------- MLP GEMM (K=1088) mma, 4-stage, fused relu*W2 (r10-proven) ----------------
__global__ void __launch_bounds__(256,2) mlp_bf(){
    extern __shared__ char dsm[];
    unsigned int* sw = (unsigned int*)dsm;
    float* sVi = (float*)(dsm + 81920);
    float* sW2 = (float*)(dsm + 84032);
    unsigned char* iIdx = (unsigned char*)(dsm + 84544);
    int nt = blockIdx.x, n0 = nt*128, m0 = blockIdx.y*128;
    int tid = threadIdx.x, lane = tid&31, warp = tid>>5;
    int wm = warp&3, wn = warp>>2;
    int i0 = m0/KANT;
    if (tid < 128){
        iIdx[tid] = (unsigned char)((m0+tid)/KANT - i0);
        sW2[tid] = d_w2p[n0+tid];
    }
    {
        int rr = tid>>6, cc = tid&63;
        int row = min(i0+rr, KSPAN-1);
        *(float2*)(sVi + rr*132 + cc*2) = *(const float2*)(d_Vi + (size_t)row*NPAD + n0 + cc*2);
    }
    float acc[2][8][4];
    #pragma unroll
    for (int a=0;a<2;a++)
        #pragma unroll
        for (int b=0;b<8;b++)
            #pragma unroll
            for (int c=0;c<4;c++) acc[a][b][c]=0.f;
    int r0 = tid>>2, c4 = tid&3;
    auto issue = [&](int k){
        int st = k & 3;
        int k0 = k*32;
        #pragma unroll
        for (int it=0; it<2; it++){
            int r = r0 + it*64;
            uint32_t base = smem_u32(sw + st*5120 + r*20 + c4*4);
            cpasync16(base,          d_A2  + (size_t)(m0+r)*KPA + k0 + c4*8);
            cpasync16(base + 2560*4, d_B2t + (size_t)(n0+r)*KPA + k0 + c4*8);
        }
        CommitG();
    };
    issue(0); issue(1); issue(2);
    const int KT = KPA/32;   // 34
    for (int kt=0; kt<KT; kt++){
        int st = kt & 3;
        if (kt+3 < KT){ issue(kt+3); WG(3); }
        else { int ah = KT-1-kt; if (ah==2) WG(2); else if (ah==1) WG(1); else WG(0); }
        __syncthreads();
        int wb = st*5120;
        #pragma unroll
        for (int ks=0; ks<2; ks++){
            unsigned int af[2][4], bfr[8][2];
            int arow = wm*32 + (lane>>2), aw = ks*8 + (lane&3);
            #pragma unroll
            for (int mi=0;mi<2;mi++){
                int base = wb + (arow+mi*16)*20;
                af[mi][0]=sw[base+aw]; af[mi][1]=sw[base+160+aw];
                af[mi][2]=sw[base+aw+4]; af[mi][3]=sw[base+160+aw+4];
            }
            int bb = wn*64 + (lane>>2);
            #pragma unroll
            for (int ni=0;ni<8;ni++){
                int base = wb + 2560 + (bb+ni*8)*20 + aw;
                bfr[ni][0]=sw[base]; bfr[ni][1]=sw[base+4];
            }
            #pragma unroll
            for (int mi=0;mi<2;mi++)
                #pragma unroll
                for (int ni=0;ni<8;ni++)
                    asm volatile("mma.sync.aligned.m16n8k16.row.col.f32.bf16.bf16.f32 "
                        "{%0,%1,%2,%3},{%4,%5,%6,%7},{%8,%9},{%0,%1,%2,%3};\n"
                        : "+f"(acc[mi][ni][0]), "+f"(acc[mi][ni][1]),
                          "+f"(acc[mi][ni][2]), "+f"(acc[mi][ni][3])
                        : "r"(af[mi][0]), "r"(af[mi][1]), "r"(af[mi][2]), "r"(af[mi][3]),
                          "r"(bfr[ni][0]), "r"(bfr[ni][1]));
        }
        __syncthreads();
    }
    int slot = nt*2 + wn;
    #pragma unroll
    for (int mi=0;mi<2;mi++){
        int rA = wm*32 + mi*16 + (lane>>2), rB = rA+8;
        const float* viA = sVi + iIdx[rA]*132;
        const float* viB = sVi + iIdx[rB]*132;
        float rs0 = 0.f, rs1 = 0.f;
        #pragma unroll
        for (int ni=0;ni<8;ni++){
            int nl = wn*64 + ni*8 + (lane&3)*2;
            float2 wv = *(const float2*)(sW2 + nl);
            float2 va = *(const float2*)(viA + nl);
            float2 vb = *(const float2*)(viB + nl);
            rs0 += fmaxf(acc[mi][ni][0]+va.x, 0.f)*wv.x + fmaxf(acc[mi][ni][1]+va.y, 0.f)*wv.y;
            rs1 += fmaxf(acc[mi][ni][2]+vb.x, 0.f)*wv.x + fmaxf(acc[mi][ni][3]+vb.y, 0.f)*wv.y;
        }
        rs0 += __shfl_xor_sync(0xffffffffu, rs0, 1);
        rs0 += __shfl_xor_sync(0xffffffffu, rs0, 2);
        rs1 += __shfl_xor_sync(0xffffffffu, rs1, 1);
        rs1 += __shfl_xor_sync(0xffffffffu, rs1, 2);
        if ((lane&3)==0){
            d_part[(size_t)slot*MROWS + m0 + rA] = rs0;
            d_part[(size_t)slot*MROWS + m0 + rB] = rs1;
        }
    }
}

__global__ void reduce_sa(){
    int m = blockIdx.x*256 + threadIdx.x;
    if (m >= MROWS) return;
    float s = 0.f;
    #pragma unroll
    for (int t=0; t<NSLOTS; t++) s += d_part[(size_t)t*MROWS + m];
    d_sa[m] = s;
}

// ---------------- refinement ----------------
__global__ void refine_kernel(const float* __restrict__ g, const float* __restrict__ b2){
    int i = blockIdx.x;
    int nv = min(i, KANT);
    __shared__ float p[KANT+1];
    __shared__ int ji[KANT];
    __shared__ float red[128];
    int tid = threadIdx.x;
    float val;
    if (tid==0) val = 0.f;
    else if (tid<=KANT){
        int kk = tid-1;
        val = (kk<nv) ? d_sa[i*KANT+kk] + b2[0] + d_bs[i*KANT+kk] : NEGV;
    } else val = NEGV;
    red[tid]=val; __syncthreads();
    for (int s=64;s>0;s>>=1){ if (tid<s) red[tid]=fmaxf(red[tid],red[tid+s]); __syncthreads(); }
    float mx = red[0]; __syncthreads();
    float e = (tid<=KANT) ? expf(val-mx) : 0.f;
    red[tid]=e; __syncthreads();
    for (int s=64;s>0;s>>=1){ if (tid<s) red[tid]+=red[tid+s]; __syncthreads(); }
    float sum = red[0];
    if (tid<=KANT) p[tid] = e/sum;
    if (tid<KANT) ji[tid] = d_bi[i*KANT+tid];
    __syncthreads();
    for (int d=tid; d<GIDIM; d+=128){
        float a = p[0]*g[(size_t)i*GIDIM+d];
        for (int kk=0;kk<nv;kk++) a += p[kk+1]*g[(size_t)ji[kk]*GIDIM+d];
        d_an[(size_t)i*GIDIM+d] = a;
    }
}

__global__ void final_kernel(const float* __restrict__ b2, float* __restrict__ out){
    int idx = blockIdx.x*256 + threadIdx.x;
    if (idx >= KSPAN*(KANT+1)) return;
    int i = idx/(KANT+1), c = idx - i*(KANT+1);
    float v;
    if (c==0) v = 0.f;
    else {
        int kk = c-1;
        if (i==0) v = (kk==0)? 0.f : NEGV;
        else      v = (kk < min(i,KANT)) ? d_sa[i*KANT+kk] + b2[0] + d_bs[i*KANT+kk] : NEGV;
    }
    out[idx] = v;
}

// ---------------- launch ----------------
extern "C" void kernel_launch(void* const* d_in, const int* in_sizes, int n_in,
                              void* d_out, int out_size){
    const float* g_i     = (const float*)d_in[0];
    const float* mention = (const float*)d_in[1];
    const float* dist_e  = (const float*)d_in[2];
    const float* genre_e = (const float*)d_in[3];
    const float* spk_e   = (const float*)d_in[4];
    const float* coarseW = (const float*)d_in[5];
    const float* W1      = (const float*)d_in[6];
    const float* b1      = (const float*)d_in[7];
    const float* W2      = (const float*)d_in[8];
    const float* b2      = (const float*)d_in[9];
    const float* Wf      = (const float*)d_in[10];
    const float* bfv     = (const float*)d_in[11];
    const int* starts    = (const int*)d_in[12];
    const int* ends      = (const int*)d_in[13];
    const int* gids      = (const int*)d_in[14];
    const int* sids      = (const int*)d_in[15];
    float* out = (float*)d_out;

    cudaFuncSetAttribute(mlp_bf, cudaFuncAttributeMaxDynamicSharedMemorySize, MLP_SMEM);

    prep_master<<<4388,256>>>(W1, Wf, b1, W2, dist_e, genre_e, spk_e);                  // 1
    gemm_f32<<<dim3(24,16),256>>>(6, g_i, coarseW, GIDIM, nullptr, nullptr, gids);      // 2: proj + Vi(it0)
    gemm_f32<<<dim3(16,16),256>>>(1, d_proj, g_i, GIDIM, mention, nullptr, nullptr);    // 3: ant
    topk_kernel<<<KSPAN,512>>>();                                                       // 4 <- profiled
    build_A<<<MROWS/8,256>>>(g_i, starts, ends, sids);                                  // 5
    mlp_bf<<<dim3(NPAD/128, MROWS/128),256,MLP_SMEM>>>();                               // 6
    reduce_sa<<<(MROWS+255)/256,256>>>();
    refine_kernel<<<KSPAN,128>>>(g_i, b2);
    gemm_f32<<<dim3(8,16),256>>>(3, g_i, d_WfTf, 1024, bfv, d_an, nullptr);             // gate -> d_gnext
    gemm_f32<<<dim3(16,16),256>>>(2, d_gnext, d_B1tf, GIDIM, nullptr, nullptr, gids);   // Vi(it1)
    build_A<<<MROWS/8,256>>>(d_gnext, starts, ends, sids);
    mlp_bf<<<dim3(NPAD/128, MROWS/128),256,MLP_SMEM>>>();
    reduce_sa<<<(MROWS+255)/256,256>>>();
    final_kernel<<<(KSPAN*(KANT+1)+255)/256,256>>>(b2, out);
}

// round 13
// speedup vs baseline: 1.7194x; 1.7194x over previous
#include <cuda_runtime.h>
#include <cuda_bf16.h>
#include <math.h>
#include <stdint.h>

#define NEGV (-1e10f)
#define KSPAN 1024
#define KANT 50
#define GIDIM 512
#define HID 1000
#define MROWS (KSPAN*KANT)   // 51200
#define KA 1024              // gate GEMM K
#define KPA 1088             // MLP GEMM K: [gj(512) | gi*gj(512) | onehot(18) pad 64]
#define NPAD 1024
#define NSLOTS 16

// 3-stage ring, 64-k chunks: per stage A 128x36w + B 128x36w = 36864B
#define STG_W 9216           // words per stage (A 4608 + B 4608)
#define RING_B 110592        // 3 stages bytes
#define BG_SMEM RING_B
#define MLP_SMEM (RING_B + 2112 + 512 + 128)   // + sVi + sW2 + iIdx = 113344

// ---------------- device scratch ----------------
__device__ __nv_bfloat16 d_gb[KSPAN*GIDIM];
__device__ __nv_bfloat16 d_gnb[KSPAN*GIDIM];
__device__ __nv_bfloat16 d_wcb[GIDIM*GIDIM];
__device__ __nv_bfloat16 d_projb[KSPAN*GIDIM];
__device__ float d_ant[KSPAN*KSPAN];
__device__ float d_bs[KSPAN*KANT];
__device__ int   d_bi[KSPAN*KANT];
__device__ __nv_bfloat16 d_A2[(size_t)MROWS*KPA];
__device__ __nv_bfloat16 d_B2t[(size_t)NPAD*KPA];     // [W1b | W1c | Vc rows | 0pad]
__device__ __nv_bfloat16 d_B1t[(size_t)NPAD*GIDIM];   // W1a^T
__device__ __nv_bfloat16 d_wft[(size_t)GIDIM*KA];
__device__ __nv_bfloat16 d_gateA[(size_t)KSPAN*KA];
__device__ float d_Vi[(size_t)KSPAN*NPAD];
__device__ float d_Vg[8*NPAD];
__device__ float d_w2p[NPAD];
__device__ float d_b1p[NPAD];
__device__ float d_part[(size_t)NSLOTS*MROWS];
__device__ float d_sa[MROWS];
__device__ float d_an[KSPAN*GIDIM];

// ---------------- helpers ----------------
__device__ __forceinline__ uint32_t smem_u32(const void* p){
    uint32_t a; asm("{ .reg .u64 t; cvta.to.shared.u64 t, %1; cvt.u32.u64 %0, t; }" : "=r"(a) : "l"(p));
    return a;
}
__device__ __forceinline__ void cpasync16(uint32_t dst, const void* src){
    asm volatile("cp.async.cg.shared.global [%0], [%1], 16;\n" :: "r"(dst), "l"(src) : "memory");
}
#define WG(n) asm volatile("cp.async.wait_group %0;\n" :: "n"(n) : "memory")
#define CommitG() asm volatile("cp.async.commit_group;\n" ::: "memory")

// ---------------- merged prep (called 3x with base offsets) ----------------
__global__ void prep_master(int base, const float* __restrict__ g, const float* __restrict__ coarseW,
                            const float* __restrict__ W1, const float* __restrict__ Wf,
                            const float* __restrict__ b1, const float* __restrict__ W2,
                            const float* __restrict__ dist_e, const float* __restrict__ genre_e,
                            const float* __restrict__ spk_e){
    int b = base + blockIdx.x, t = threadIdx.x;
    if (b < 2048){
        int i = b*256 + t; d_gb[i] = __float2bfloat16(g[i]);
    } else if (b < 3072){
        int i = (b-2048)*256 + t; d_wcb[i] = __float2bfloat16(coarseW[i]);
    } else if (b < 5120){
        int idx = (b-3072)*256 + t;          // over NPAD*512
        int n = idx >> 9, k = idx & 511;
        float a=0.f, bb=0.f, c=0.f;
        if (n < HID){
            a  = W1[(size_t)k*HID + n];
            bb = W1[(size_t)(512+k)*HID + n];
            c  = W1[(size_t)(1024+k)*HID + n];
        }
        d_B1t[(size_t)n*GIDIM + k] = __float2bfloat16(a);
        d_B2t[(size_t)n*KPA + k]       = __float2bfloat16(bb);
        d_B2t[(size_t)n*KPA + 512 + k] = __float2bfloat16(c);
    } else if (b < 5376){
        int idx = (b-5120)*256 + t;          // over NPAD*64
        int n = idx >> 6, c = idx & 63;
        float s = 0.f;
        if (c < 18 && n < HID){
            int bin = c>>1, lab = (c&1)+1;
            for (int k=0;k<20;k++) s += dist_e[bin*20+k]*W1[(size_t)(1536+k)*HID+n]
                                      + spk_e[lab*20+k]*W1[(size_t)(1576+k)*HID+n];
        }
        d_B2t[(size_t)n*KPA + 1024 + c] = __float2bfloat16(s);
    } else if (b < 7424){
        int idx = (b-5376)*256 + t;
        int n = idx >> 10, k = idx & 1023;
        d_wft[idx] = __float2bfloat16(Wf[(size_t)k*GIDIM + n]);
    } else if (b < 7428){
        int n = (b-7424)*256 + t;
        d_w2p[n] = (n<HID)? W2[n]:0.f; d_b1p[n] = (n<HID)? b1[n]:0.f;
    } else {
        int idx = (b-7428)*256 + t;          // over 8*1024
        int row = idx >> 10, n = idx & 1023;
        float s = 0.f;
        if (n < HID)
            for (int k=0;k<20;k++) s += genre_e[row*20+k]*W1[(size_t)(1556+k)*HID+n];
        d_Vg[row*NPAD+n] = s;
    }
}

// ---------------- core 64-k-chunk mainloop (macro used by both GEMM kernels) ----------------
// consumes stage kt%3 of ring sw; layout: row*36 words + ks*8 + (lane&3)
#define CONSUME_STAGE(wb)                                                                     \
    _Pragma("unroll")                                                                         \
    for (int ks=0; ks<4; ks++){                                                               \
        unsigned int af[2][4], bfr[8][2];                                                     \
        int aw = ks*8 + (lane&3);                                                             \
        _Pragma("unroll")                                                                     \
        for (int mi=0;mi<2;mi++){                                                             \
            int base = (wb) + (arow+mi*16)*36;                                                \
            af[mi][0]=sw[base+aw]; af[mi][1]=sw[base+288+aw];                                 \
            af[mi][2]=sw[base+aw+4]; af[mi][3]=sw[base+288+aw+4];                             \
        }                                                                                     \
        _Pragma("unroll")                                                                     \
        for (int ni=0;ni<8;ni++){                                                             \
            int base = (wb) + 4608 + (bb0+ni*8)*36 + aw;                                      \
            bfr[ni][0]=sw[base]; bfr[ni][1]=sw[base+4];                                       \
        }                                                                                     \
        _Pragma("unroll")                                                                     \
        for (int mi=0;mi<2;mi++)                                                              \
            _Pragma("unroll")                                                                 \
            for (int ni=0;ni<8;ni++)                                                          \
                asm volatile("mma.sync.aligned.m16n8k16.row.col.f32.bf16.bf16.f32 "           \
                    "{%0,%1,%2,%3},{%4,%5,%6,%7},{%8,%9},{%0,%1,%2,%3};\n"                    \
                    : "+f"(acc[mi][ni][0]), "+f"(acc[mi][ni][1]),                             \
                      "+f"(acc[mi][ni][2]), "+f"(acc[mi][ni][3])                              \
                    : "r"(af[mi][0]), "r"(af[mi][1]), "r"(af[mi][2]), "r"(af[mi][3]),         \
                      "r"(bfr[ni][0]), "r"(bfr[ni][1]));                                      \
    }

// ---------------- bf16 mma GEMM (128x128), 3-stage/64k/1-barrier ----------------
// modes: 1 ant+mask | 2 Vi | 3 gate | 6 fused proj(bx<4)+Vi(bx>=4)
__global__ void __launch_bounds__(256,2) bgemm(int mode, const __nv_bfloat16* __restrict__ A,
        const __nv_bfloat16* __restrict__ B, int Kdim,
        const float* __restrict__ aux0, const float* __restrict__ aux1,
        const int* __restrict__ auxi){
    extern __shared__ char dsm[];
    unsigned int* sw = (unsigned int*)dsm;
    int bx = blockIdx.x;
    const __nv_bfloat16* Bp = B;
    bool m6proj = false;
    int n0;
    if (mode == 6){
        m6proj = (bx < 4);
        Bp = m6proj ? d_wcb : d_B1t;
        n0 = (m6proj ? bx : bx-4)*128;
    } else n0 = bx*128;
    int m0 = blockIdx.y*128;
    int tid = threadIdx.x, lane = tid&31, warp = tid>>5;
    int wm = warp&3, wn = warp>>2;
    int arow = wm*32 + (lane>>2);
    int bb0 = wn*64 + (lane>>2);
    float acc[2][8][4];
    #pragma unroll
    for (int a=0;a<2;a++)
        #pragma unroll
        for (int b=0;b<8;b++)
            #pragma unroll
            for (int c=0;c<4;c++) acc[a][b][c]=0.f;
    int r8 = tid>>3, c8 = tid&7;
    auto issue = [&](int k){
        int st = k % 3;
        int k0 = k*64;
        uint32_t sa = smem_u32(sw + st*STG_W) + r8*144 + c8*16;
        #pragma unroll
        for (int it=0; it<4; it++){
            int r = r8 + it*32;
            cpasync16(sa + it*32*144,           A  + (size_t)(m0+r)*Kdim + k0 + c8*8);
            cpasync16(sa + 4608*4 + it*32*144,  Bp + (size_t)(n0+r)*Kdim + k0 + c8*8);
        }
        CommitG();
    };
    issue(0); issue(1);
    int KT = Kdim/64;
    for (int kt=0; kt<KT; kt++){
        if (kt+2 < KT) WG(1); else WG(0);
        __syncthreads();
        if (kt+2 < KT) issue(kt+2);
        int wb = (kt%3)*STG_W;
        CONSUME_STAGE(wb)
    }
    #pragma unroll
    for (int mi=0;mi<2;mi++)
        #pragma unroll
        for (int ni=0;ni<8;ni++)
            #pragma unroll
            for (int q=0;q<4;q++){
                int m = m0 + wm*32 + mi*16 + (lane>>2) + ((q>=2)?8:0);
                int n = n0 + wn*64 + ni*8 + (lane&3)*2 + (q&1);
                float v = acc[mi][ni][q];
                if (mode==6 && m6proj) d_projb[(size_t)m*GIDIM+n] = __float2bfloat16(v);
                else if (mode==1){
                    v += aux0[m] + aux0[n];
                    if (n >= m) v += NEGV;
                    d_ant[(size_t)m*KSPAN+n] = v;
                } else if (mode==2 || mode==6){
                    d_Vi[(size_t)m*NPAD+n] = v + d_b1p[n] + d_Vg[auxi[m]*NPAD+n];
                } else {
                    float f = 1.f/(1.f+expf(-(v+aux0[n])));
                    float gv = aux1[(size_t)m*GIDIM+n];
                    float av = d_an[(size_t)m*GIDIM+n];
                    float o = (m==0)? gv : f*gv + (1.f-f)*av;
                    d_gnb[(size_t)m*GIDIM+n] = __float2bfloat16(o);
                }
            }
}

// ---------------- top-K bitonic ----------------
__global__ void topk_kernel(){
    int row = blockIdx.x;
    __shared__ unsigned long long sk[1024];
    for (int j=threadIdx.x; j<1024; j+=512){
        unsigned int b = __float_as_uint(d_ant[(size_t)row*KSPAN+j]);
        unsigned int asc = (b & 0x80000000u) ? ~b : (b | 0x80000000u);
        sk[j] = (((unsigned long long)(~asc))<<32) | (unsigned int)j;
    }
    __syncthreads();
    for (int k=2;k<=1024;k<<=1)
        for (int j=k>>1;j>0;j>>=1){
            for (int i=threadIdx.x;i<1024;i+=512){
                int ixj = i^j;
                if (ixj>i){
                    bool up = ((i&k)==0);
                    unsigned long long a=sk[i], b=sk[ixj];
                    if ((a>b)==up){ sk[i]=b; sk[ixj]=a; }
                }
            }
            __syncthreads();
        }
    if (threadIdx.x < KANT){
        int j = (int)(sk[threadIdx.x] & 0xffffffffu);
        d_bi[row*KANT+threadIdx.x] = j;
        d_bs[row*KANT+threadIdx.x] = d_ant[(size_t)row*KSPAN+j];
    }
}

// ---------------- build A2 = [gj | gi*gj | onehot18 | 0pad] ----------------
__global__ void build_A(int it, const int* __restrict__ starts, const int* __restrict__ ends,
                        const int* __restrict__ sids){
    const __nv_bfloat16* g = it ? d_gnb : d_gb;
    int warp = threadIdx.x>>5, lane = threadIdx.x&31;
    int r = blockIdx.x*8 + warp;
    int i = r/KANT, j = d_bi[r];
    const uint4* gi4 = (const uint4*)(g + (size_t)i*GIDIM);
    const uint4* gj4 = (const uint4*)(g + (size_t)j*GIDIM);
    uint4 a0 = gi4[lane*2], a1 = gi4[lane*2+1];
    uint4 b0 = gj4[lane*2], b1 = gj4[lane*2+1];
    uint4 p0, p1;
    {
        const __nv_bfloat162* ap = (const __nv_bfloat162*)&a0;
        const __nv_bfloat162* bp = (const __nv_bfloat162*)&b0;
        __nv_bfloat162* pp = (__nv_bfloat162*)&p0;
        #pragma unroll
        for (int w=0; w<4; w++) pp[w] = __hmul2(ap[w], bp[w]);
        ap = (const __nv_bfloat162*)&a1; bp = (const __nv_bfloat162*)&b1;
        pp = (__nv_bfloat162*)&p1;
        #pragma unroll
        for (int w=0; w<4; w++) pp[w] = __hmul2(ap[w], bp[w]);
    }
    __nv_bfloat16* Ar = d_A2 + (size_t)r*KPA;
    ((uint4*)Ar)[lane*2]   = b0;
    ((uint4*)Ar)[lane*2+1] = b1;
    ((uint4*)(Ar+512))[lane*2]   = p0;
    ((uint4*)(Ar+512))[lane*2+1] = p1;
    if (lane < 8){
        int d = ends[i]-starts[j];
        int bin = (d>1)+(d>2)+(d>3)+(d>4)+(d>8)+(d>16)+(d>32)+(d>64);
        int lab = (sids[i]==sids[j]) ? 1 : 2;
        int meta = bin*2 + lab - 1;        // 0..17
        uint4 z = make_uint4(0,0,0,0);
        int dd = meta - lane*8;
        if (dd >= 0 && dd < 8){
            unsigned int val = 0x3F80u << (16*(dd&1));
            ((unsigned int*)&z)[dd>>1] = val;
        }
        ((uint4*)(Ar+1024))[lane] = z;     // covers cols 1024..1087
    }
}

// ---------------- MLP GEMM (K=1088), 3-stage/64k/1-barrier + fused relu*W2 ----------------
__global__ void __launch_bounds__(256,2) mlp_bf(){
    extern __shared__ char dsm[];
    unsigned int* sw = (unsigned int*)dsm;
    float* sVi = (float*)(dsm + RING_B);
    float* sW2 = (float*)(dsm + RING_B + 2112);
    unsigned char* iIdx = (unsigned char*)(dsm + RING_B + 2624);
    int nt = blockIdx.x, n0 = nt*128, m0 = blockIdx.y*128;
    int tid = threadIdx.x, lane = tid&31, warp = tid>>5;
    int wm = warp&3, wn = warp>>2;
    int arow = wm*32 + (lane>>2);
    int bb0 = wn*64 + (lane>>2);
    int i0 = m0/KANT;
    if (tid < 128){
        iIdx[tid] = (unsigned char)((m0+tid)/KANT - i0);
        sW2[tid] = d_w2p[n0+tid];
    }
    {
        int rr = tid>>6, cc = tid&63;
        int row = min(i0+rr, KSPAN-1);
        *(float2*)(sVi + rr*132 + cc*2) = *(const float2*)(d_Vi + (size_t)row*NPAD + n0 + cc*2);
    }
    float acc[2][8][4];
    #pragma unroll
    for (int a=0;a<2;a++)
        #pragma unroll
        for (int b=0;b<8;b++)
            #pragma unroll
            for (int c=0;c<4;c++) acc[a][b][c]=0.f;
    int r8 = tid>>3, c8 = tid&7;
    auto issue = [&](int k){
        int st = k % 3;
        int k0 = k*64;
        uint32_t sa = smem_u32(sw + st*STG_W) + r8*144 + c8*16;
        #pragma unroll
        for (int it=0; it<4; it++){
            int r = r8 + it*32;
            cpasync16(sa + it*32*144,           d_A2  + (size_t)(m0+r)*KPA + k0 + c8*8);
            cpasync16(sa + 4608*4 + it*32*144,  d_B2t + (size_t)(n0+r)*KPA + k0 + c8*8);
        }
        CommitG();
    };
    issue(0); issue(1);
    const int KT = KPA/64;   // 17
    for (int kt=0; kt<KT; kt++){
        if (kt+2 < KT) WG(1); else WG(0);
        __syncthreads();
        if (kt+2 < KT) issue(kt+2);
        int wb = (kt%3)*STG_W;
        CONSUME_STAGE(wb)
    }
    // epilogue: h = acc + Vi(smem); rs += relu(h)*w2(smem)
    int slot = nt*2 + wn;
    #pragma unroll
    for (int mi=0;mi<2;mi++){
        int rA = wm*32 + mi*16 + (lane>>2), rB = rA+8;
        const float* viA = sVi + iIdx[rA]*132;
        const float* viB = sVi + iIdx[rB]*132;
        float rs0 = 0.f, rs1 = 0.f;
        #pragma unroll
        for (int ni=0;ni<8;ni++){
            int nl = wn*64 + ni*8 + (lane&3)*2;
            float2 wv = *(const float2*)(sW2 + nl);
            float2 va = *(const float2*)(viA + nl);
            float2 vb = *(const float2*)(viB + nl);
            rs0 += fmaxf(acc[mi][ni][0]+va.x, 0.f)*wv.x + fmaxf(acc[mi][ni][1]+va.y, 0.f)*wv.y;
            rs1 += fmaxf(acc[mi][ni][2]+vb.x, 0.f)*wv.x + fmaxf(acc[mi][ni][3]+vb.y, 0.f)*wv.y;
        }
        rs0 += __shfl_xor_sync(0xffffffffu, rs0, 1);
        rs0 += __shfl_xor_sync(0xffffffffu, rs0, 2);
        rs1 += __shfl_xor_sync(0xffffffffu, rs1, 1);
        rs1 += __shfl_xor_sync(0xffffffffu, rs1, 2);
        if ((lane&3)==0){
            d_part[(size_t)slot*MROWS + m0 + rA] = rs0;
            d_part[(size_t)slot*MROWS + m0 + rB] = rs1;
        }
    }
}

__global__ void reduce_sa(){
    int m = blockIdx.x*256 + threadIdx.x;
    if (m >= MROWS) return;
    float s = 0.f;
    #pragma unroll
    for (int t=0; t<NSLOTS; t++) s += d_part[(size_t)t*MROWS + m];
    d_sa[m] = s;
}

// ---------------- refinement ----------------
__global__ void refine_kernel(const float* __restrict__ g, const float* __restrict__ b2){
    int i = blockIdx.x;
    int nv = min(i, KANT);
    __shared__ float p[KANT+1];
    __shared__ int ji[KANT];
    __shared__ float red[128];
    int tid = threadIdx.x;
    float val;
    if (tid==0) val = 0.f;
    else if (tid<=KANT){
        int kk = tid-1;
        val = (kk<nv) ? d_sa[i*KANT+kk] + b2[0] + d_bs[i*KANT+kk] : NEGV;
    } else val = NEGV;
    red[tid]=val; __syncthreads();
    for (int s=64;s>0;s>>=1){ if (tid<s) red[tid]=fmaxf(red[tid],red[tid+s]); __syncthreads(); }
    float mx = red[0]; __syncthreads();
    float e = (tid<=KANT) ? expf(val-mx) : 0.f;
    red[tid]=e; __syncthreads();
    for (int s=64;s>0;s>>=1){ if (tid<s) red[tid]+=red[tid+s]; __syncthreads(); }
    float sum = red[0];
    if (tid<=KANT) p[tid] = e/sum;
    if (tid<KANT) ji[tid] = d_bi[i*KANT+tid];
    __syncthreads();
    for (int d=tid; d<GIDIM; d+=128){
        float a = p[0]*g[(size_t)i*GIDIM+d];
        for (int kk=0;kk<nv;kk++) a += p[kk+1]*g[(size_t)ji[kk]*GIDIM+d];
        d_an[(size_t)i*GIDIM+d] = a;
    }
}

__global__ void build_gateA(const float* __restrict__ g){
    int idx = blockIdx.x*256 + threadIdx.x;
    if (idx >= KSPAN*GIDIM) return;
    int m = idx/GIDIM, d = idx - m*GIDIM;
    d_gateA[(size_t)m*KA + d]         = __float2bfloat16(g[idx]);
    d_gateA[(size_t)m*KA + GIDIM + d] = __float2bfloat16(d_an[idx]);
}

__global__ void final_kernel(const float* __restrict__ b2, float* __restrict__ out){
    int idx = blockIdx.x*256 + threadIdx.x;
    if (idx >= KSPAN*(KANT+1)) return;
    int i = idx/(KANT+1), c = idx - i*(KANT+1);
    float v;
    if (c==0) v = 0.f;
    else {
        int kk = c-1;
        if (i==0) v = (kk==0)? 0.f : NEGV;
        else      v = (kk < min(i,KANT)) ? d_sa[i*KANT+kk] + b2[0] + d_bs[i*KANT+kk] : NEGV;
    }
    out[idx] = v;
}

// ---------------- launch ----------------
extern "C" void kernel_launch(void* const* d_in, const int* in_sizes, int n_in,
                              void* d_out, int out_size){
    const float* g_i     = (const float*)d_in[0];
    const float* mention = (const float*)d_in[1];
    const float* dist_e  = (const float*)d_in[2];
    const float* genre_e = (const float*)d_in[3];
    const float* spk_e   = (const float*)d_in[4];
    const float* coarseW = (const float*)d_in[5];
    const float* W1      = (const float*)d_in[6];
    const float* b1      = (const float*)d_in[7];
    const float* W2      = (const float*)d_in[8];
    const float* b2      = (const float*)d_in[9];
    const float* Wf      = (const float*)d_in[10];
    const float* bfv     = (const float*)d_in[11];
    const int* starts    = (const int*)d_in[12];
    const int* ends      = (const int*)d_in[13];
    const int* gids      = (const int*)d_in[14];
    const int* sids      = (const int*)d_in[15];
    float* out = (float*)d_out;

    cudaFuncSetAttribute(bgemm, cudaFuncAttributeMaxDynamicSharedMemorySize, BG_SMEM);
    cudaFuncSetAttribute(mlp_bf, cudaFuncAttributeMaxDynamicSharedMemorySize, MLP_SMEM);

    prep_master<<<3072,256>>>(0,    g_i, coarseW, W1, Wf, b1, W2, dist_e, genre_e, spk_e); // 1
    prep_master<<<2304,256>>>(3072, g_i, coarseW, W1, Wf, b1, W2, dist_e, genre_e, spk_e); // 2
    prep_master<<<2084,256>>>(5376, g_i, coarseW, W1, Wf, b1, W2, dist_e, genre_e, spk_e); // 3
    bgemm<<<dim3(12, 8),256,BG_SMEM>>>(6, d_gb, nullptr, GIDIM, nullptr, nullptr, gids);   // 4 <- profiled
    bgemm<<<dim3(8, 8),256,BG_SMEM>>>(1, d_projb, d_gb, GIDIM, mention, nullptr, nullptr); // 5
    topk_kernel<<<KSPAN,512>>>();                                                          // 6
    build_A<<<MROWS/8,256>>>(0, starts, ends, sids);                                       // 7
    mlp_bf<<<dim3(NPAD/128, MROWS/128),256,MLP_SMEM>>>();                                  // 8
    reduce_sa<<<(MROWS+255)/256,256>>>();
    refine_kernel<<<KSPAN,128>>>(g_i, b2);
    build_gateA<<<(KSPAN*GIDIM+255)/256,256>>>(g_i);
    bgemm<<<dim3(4, 8),256,BG_SMEM>>>(3, d_gateA, d_wft, KA, bfv, g_i, nullptr);
    // iteration 1
    bgemm<<<dim3(8, 8),256,BG_SMEM>>>(2, d_gnb, d_B1t, GIDIM, nullptr, nullptr, gids);
    build_A<<<MROWS/8,256>>>(1, starts, ends, sids);
    mlp_bf<<<dim3(NPAD/128, MROWS/128),256,MLP_SMEM>>>();
    reduce_sa<<<(MROWS+255)/256,256>>>();
    final_kernel<<<(KSPAN*(KANT+1)+255)/256,256>>>(b2, out);
}

// round 14
// speedup vs baseline: 1.9875x; 1.1559x over previous
#include <cuda_runtime.h>
#include <cuda_bf16.h>
#include <math.h>
#include <stdint.h>

#define NEGV (-1e10f)
#define KSPAN 1024
#define KANT 50
#define GIDIM 512
#define HID 1000
#define MROWS (KSPAN*KANT)   // 51200
#define KA 1024              // gate GEMM K
#define KPA 576              // MLP K: [gi*gj(512) | onehot18 | pad] -> 9 chunks of 64
#define NPAD 1024
#define NSLOTS 16

#define STG_W 9216           // words per stage (A 4608 + B 4608), 64-k chunk
#define RING_B 110592        // 3 stages
#define BG_SMEM RING_B
#define MLP_SMEM (RING_B + 2112 + 512 + 128)   // + sVi + sW2 + iIdx

// ---------------- device scratch ----------------
__device__ __nv_bfloat16 d_gb[KSPAN*GIDIM];
__device__ __nv_bfloat16 d_gnb[KSPAN*GIDIM];
__device__ __nv_bfloat16 d_wcb[GIDIM*GIDIM];
__device__ __nv_bfloat16 d_projb[KSPAN*GIDIM];
__device__ float d_ant[KSPAN*KSPAN];
__device__ float d_bs[KSPAN*KANT];
__device__ int   d_bi[KSPAN*KANT];
__device__ __nv_bfloat16 d_A2[(size_t)MROWS*KPA];
__device__ __nv_bfloat16 d_B2t[(size_t)NPAD*KPA];     // [W1c | Vc rows | 0pad]
__device__ __nv_bfloat16 d_B1t[(size_t)NPAD*GIDIM];   // W1a^T
__device__ __nv_bfloat16 d_Bjt[(size_t)NPAD*GIDIM];   // W1b^T
__device__ __nv_bfloat16 d_Vjb[(size_t)KSPAN*NPAD];   // Vj = g@W1b^T (bf16)
__device__ __nv_bfloat16 d_wft[(size_t)GIDIM*KA];
__device__ __nv_bfloat16 d_gateA[(size_t)KSPAN*KA];
__device__ float d_Vi[(size_t)KSPAN*NPAD];
__device__ float d_Vg[8*NPAD];
__device__ float d_w2p[NPAD];
__device__ float d_b1p[NPAD];
__device__ float d_part[(size_t)NSLOTS*MROWS];
__device__ float d_sa[MROWS];
__device__ float d_an[KSPAN*GIDIM];

// ---------------- helpers ----------------
__device__ __forceinline__ uint32_t smem_u32(const void* p){
    uint32_t a; asm("{ .reg .u64 t; cvta.to.shared.u64 t, %1; cvt.u32.u64 %0, t; }" : "=r"(a) : "l"(p));
    return a;
}
__device__ __forceinline__ void cpasync16(uint32_t dst, const void* src){
    asm volatile("cp.async.cg.shared.global [%0], [%1], 16;\n" :: "r"(dst), "l"(src) : "memory");
}
#define WG(n) asm volatile("cp.async.wait_group %0;\n" :: "n"(n) : "memory")
#define CommitG() asm volatile("cp.async.commit_group;\n" ::: "memory")

// ---------------- merged prep (called 3x with base offsets) ----------------
__global__ void prep_master(int base, const float* __restrict__ g, const float* __restrict__ coarseW,
                            const float* __restrict__ W1, const float* __restrict__ Wf,
                            const float* __restrict__ b1, const float* __restrict__ W2,
                            const float* __restrict__ dist_e, const float* __restrict__ genre_e,
                            const float* __restrict__ spk_e){
    int b = base + blockIdx.x, t = threadIdx.x;
    if (b < 2048){
        int i = b*256 + t; d_gb[i] = __float2bfloat16(g[i]);
    } else if (b < 3072){
        int i = (b-2048)*256 + t; d_wcb[i] = __float2bfloat16(coarseW[i]);
    } else if (b < 5120){
        int idx = (b-3072)*256 + t;          // over NPAD*512
        int n = idx >> 9, k = idx & 511;
        float a=0.f, bb=0.f, c=0.f;
        if (n < HID){
            a  = W1[(size_t)k*HID + n];
            bb = W1[(size_t)(512+k)*HID + n];
            c  = W1[(size_t)(1024+k)*HID + n];
        }
        d_B1t[(size_t)n*GIDIM + k] = __float2bfloat16(a);
        d_Bjt[(size_t)n*GIDIM + k] = __float2bfloat16(bb);
        d_B2t[(size_t)n*KPA + k]   = __float2bfloat16(c);
    } else if (b < 5376){
        int idx = (b-5120)*256 + t;          // over NPAD*64
        int n = idx >> 6, c = idx & 63;
        float s = 0.f;
        if (c < 18 && n < HID){
            int bin = c>>1, lab = (c&1)+1;
            for (int k=0;k<20;k++) s += dist_e[bin*20+k]*W1[(size_t)(1536+k)*HID+n]
                                      + spk_e[lab*20+k]*W1[(size_t)(1576+k)*HID+n];
        }
        d_B2t[(size_t)n*KPA + 512 + c] = __float2bfloat16(s);
    } else if (b < 7424){
        int idx = (b-5376)*256 + t;
        int n = idx >> 10, k = idx & 1023;
        d_wft[idx] = __float2bfloat16(Wf[(size_t)k*GIDIM + n]);
    } else if (b < 7428){
        int n = (b-7424)*256 + t;
        d_w2p[n] = (n<HID)? W2[n]:0.f; d_b1p[n] = (n<HID)? b1[n]:0.f;
    } else {
        int idx = (b-7428)*256 + t;          // over 8*1024
        int row = idx >> 10, n = idx & 1023;
        float s = 0.f;
        if (n < HID)
            for (int k=0;k<20;k++) s += genre_e[row*20+k]*W1[(size_t)(1556+k)*HID+n];
        d_Vg[row*NPAD+n] = s;
    }
}

// ---------------- core 64-k-chunk consume (shared macro) ----------------
#define CONSUME_STAGE(wb)                                                                     \
    _Pragma("unroll")                                                                         \
    for (int ks=0; ks<4; ks++){                                                               \
        unsigned int af[2][4], bfr[8][2];                                                     \
        int aw = ks*8 + (lane&3);                                                             \
        _Pragma("unroll")                                                                     \
        for (int mi=0;mi<2;mi++){                                                             \
            int base = (wb) + (arow+mi*16)*36;                                                \
            af[mi][0]=sw[base+aw]; af[mi][1]=sw[base+288+aw];                                 \
            af[mi][2]=sw[base+aw+4]; af[mi][3]=sw[base+288+aw+4];                             \
        }                                                                                     \
        _Pragma("unroll")                                                                     \
        for (int ni=0;ni<8;ni++){                                                             \
            int base = (wb) + 4608 + (bb0+ni*8)*36 + aw;                                      \
            bfr[ni][0]=sw[base]; bfr[ni][1]=sw[base+4];                                       \
        }                                                                                     \
        _Pragma("unroll")                                                                     \
        for (int mi=0;mi<2;mi++)                                                              \
            _Pragma("unroll")                                                                 \
            for (int ni=0;ni<8;ni++)                                                          \
                asm volatile("mma.sync.aligned.m16n8k16.row.col.f32.bf16.bf16.f32 "           \
                    "{%0,%1,%2,%3},{%4,%5,%6,%7},{%8,%9},{%0,%1,%2,%3};\n"                    \
                    : "+f"(acc[mi][ni][0]), "+f"(acc[mi][ni][1]),                             \
                      "+f"(acc[mi][ni][2]), "+f"(acc[mi][ni][3])                              \
                    : "r"(af[mi][0]), "r"(af[mi][1]), "r"(af[mi][2]), "r"(af[mi][3]),         \
                      "r"(bfr[ni][0]), "r"(bfr[ni][1]));                                      \
    }

// ---------------- bf16 mma GEMM (128x128), 3-stage/64k/1-barrier ----------------
// modes: 1 ant+mask | 3 gate | 6 iter0: proj(bx<4)+Vi(4..11)+Vj(12..19) | 7 iter1: Vi(bx<8)+Vj(8..15)
__global__ void __launch_bounds__(256,2) bgemm(int mode, const __nv_bfloat16* __restrict__ A,
        const __nv_bfloat16* __restrict__ B, int Kdim,
        const float* __restrict__ aux0, const float* __restrict__ aux1,
        const int* __restrict__ auxi){
    extern __shared__ char dsm[];
    unsigned int* sw = (unsigned int*)dsm;
    int bx = blockIdx.x;
    const __nv_bfloat16* Bp = B;
    int sel = -1;   // 0 proj, 1 Vi, 2 Vj
    int n0;
    if (mode == 6){
        sel = (bx < 4) ? 0 : (bx < 12 ? 1 : 2);
        Bp = (sel==0) ? d_wcb : (sel==1 ? d_B1t : d_Bjt);
        n0 = ((sel==0) ? bx : (sel==1 ? bx-4 : bx-12))*128;
    } else if (mode == 7){
        sel = (bx < 8) ? 1 : 2;
        Bp = (sel==1) ? d_B1t : d_Bjt;
        n0 = ((sel==1) ? bx : bx-8)*128;
    } else n0 = bx*128;
    int m0 = blockIdx.y*128;
    int tid = threadIdx.x, lane = tid&31, warp = tid>>5;
    int wm = warp&3, wn = warp>>2;
    int arow = wm*32 + (lane>>2);
    int bb0 = wn*64 + (lane>>2);
    float acc[2][8][4];
    #pragma unroll
    for (int a=0;a<2;a++)
        #pragma unroll
        for (int b=0;b<8;b++)
            #pragma unroll
            for (int c=0;c<4;c++) acc[a][b][c]=0.f;
    int r8 = tid>>3, c8 = tid&7;
    auto issue = [&](int k){
        int st = k % 3;
        int k0 = k*64;
        uint32_t sa = smem_u32(sw + st*STG_W) + r8*144 + c8*16;
        #pragma unroll
        for (int it=0; it<4; it++){
            int r = r8 + it*32;
            cpasync16(sa + it*32*144,           A  + (size_t)(m0+r)*Kdim + k0 + c8*8);
            cpasync16(sa + 4608*4 + it*32*144,  Bp + (size_t)(n0+r)*Kdim + k0 + c8*8);
        }
        CommitG();
    };
    issue(0); issue(1);
    int KT = Kdim/64;
    for (int kt=0; kt<KT; kt++){
        if (kt+2 < KT) WG(1); else WG(0);
        __syncthreads();
        if (kt+2 < KT) issue(kt+2);
        int wb = (kt%3)*STG_W;
        CONSUME_STAGE(wb)
    }
    #pragma unroll
    for (int mi=0;mi<2;mi++)
        #pragma unroll
        for (int ni=0;ni<8;ni++)
            #pragma unroll
            for (int q=0;q<4;q++){
                int m = m0 + wm*32 + mi*16 + (lane>>2) + ((q>=2)?8:0);
                int n = n0 + wn*64 + ni*8 + (lane&3)*2 + (q&1);
                float v = acc[mi][ni][q];
                if (sel==0) d_projb[(size_t)m*GIDIM+n] = __float2bfloat16(v);
                else if (sel==1) d_Vi[(size_t)m*NPAD+n] = v + d_b1p[n] + d_Vg[auxi[m]*NPAD+n];
                else if (sel==2) d_Vjb[(size_t)m*NPAD+n] = __float2bfloat16(v);
                else if (mode==1){
                    v += aux0[m] + aux0[n];
                    if (n >= m) v += NEGV;
                    d_ant[(size_t)m*KSPAN+n] = v;
                } else {
                    float f = 1.f/(1.f+expf(-(v+aux0[n])));
                    float gv = aux1[(size_t)m*GIDIM+n];
                    float av = d_an[(size_t)m*GIDIM+n];
                    float o = (m==0)? gv : f*gv + (1.f-f)*av;
                    d_gnb[(size_t)m*GIDIM+n] = __float2bfloat16(o);
                }
            }
}

// ---------------- top-K bitonic ----------------
__global__ void topk_kernel(){
    int row = blockIdx.x;
    __shared__ unsigned long long sk[1024];
    for (int j=threadIdx.x; j<1024; j+=512){
        unsigned int b = __float_as_uint(d_ant[(size_t)row*KSPAN+j]);
        unsigned int asc = (b & 0x80000000u) ? ~b : (b | 0x80000000u);
        sk[j] = (((unsigned long long)(~asc))<<32) | (unsigned int)j;
    }
    __syncthreads();
    for (int k=2;k<=1024;k<<=1)
        for (int j=k>>1;j>0;j>>=1){
            for (int i=threadIdx.x;i<1024;i+=512){
                int ixj = i^j;
                if (ixj>i){
                    bool up = ((i&k)==0);
                    unsigned long long a=sk[i], b=sk[ixj];
                    if ((a>b)==up){ sk[i]=b; sk[ixj]=a; }
                }
            }
            __syncthreads();
        }
    if (threadIdx.x < KANT){
        int j = (int)(sk[threadIdx.x] & 0xffffffffu);
        d_bi[row*KANT+threadIdx.x] = j;
        d_bs[row*KANT+threadIdx.x] = d_ant[(size_t)row*KSPAN+j];
    }
}

// ---------------- build A2 = [gi*gj | onehot18 | 0pad] (576 cols) ----------------
__global__ void build_A(int it, const int* __restrict__ starts, const int* __restrict__ ends,
                        const int* __restrict__ sids){
    const __nv_bfloat16* g = it ? d_gnb : d_gb;
    int warp = threadIdx.x>>5, lane = threadIdx.x&31;
    int r = blockIdx.x*8 + warp;
    int i = r/KANT, j = d_bi[r];
    const uint4* gi4 = (const uint4*)(g + (size_t)i*GIDIM);
    const uint4* gj4 = (const uint4*)(g + (size_t)j*GIDIM);
    uint4 a0 = gi4[lane*2], a1 = gi4[lane*2+1];
    uint4 b0 = gj4[lane*2], b1 = gj4[lane*2+1];
    uint4 p0, p1;
    {
        const __nv_bfloat162* ap = (const __nv_bfloat162*)&a0;
        const __nv_bfloat162* bp = (const __nv_bfloat162*)&b0;
        __nv_bfloat162* pp = (__nv_bfloat162*)&p0;
        #pragma unroll
        for (int w=0; w<4; w++) pp[w] = __hmul2(ap[w], bp[w]);
        ap = (const __nv_bfloat162*)&a1; bp = (const __nv_bfloat162*)&b1;
        pp = (__nv_bfloat162*)&p1;
        #pragma unroll
        for (int w=0; w<4; w++) pp[w] = __hmul2(ap[w], bp[w]);
    }
    __nv_bfloat16* Ar = d_A2 + (size_t)r*KPA;
    ((uint4*)Ar)[lane*2]   = p0;
    ((uint4*)Ar)[lane*2+1] = p1;
    if (lane < 8){
        int d = ends[i]-starts[j];
        int bin = (d>1)+(d>2)+(d>3)+(d>4)+(d>8)+(d>16)+(d>32)+(d>64);
        int lab = (sids[i]==sids[j]) ? 1 : 2;
        int meta = bin*2 + lab - 1;        // 0..17
        uint4 z = make_uint4(0,0,0,0);
        int dd = meta - lane*8;
        if (dd >= 0 && dd < 8){
            unsigned int val = 0x3F80u << (16*(dd&1));
            ((unsigned int*)&z)[dd>>1] = val;
        }
        ((uint4*)(Ar+512))[lane] = z;      // cols 512..575
    }
}

// ---------------- MLP GEMM (K=576), 3-stage/64k/1-barrier + fused epilogue ----------------
__global__ void __launch_bounds__(256,2) mlp_bf(){
    extern __shared__ char dsm[];
    unsigned int* sw = (unsigned int*)dsm;
    float* sVi = (float*)(dsm + RING_B);
    float* sW2 = (float*)(dsm + RING_B + 2112);
    unsigned char* iIdx = (unsigned char*)(dsm + RING_B + 2624);
    int nt = blockIdx.x, n0 = nt*128, m0 = blockIdx.y*128;
    int tid = threadIdx.x, lane = tid&31, warp = tid>>5;
    int wm = warp&3, wn = warp>>2;
    int arow = wm*32 + (lane>>2);
    int bb0 = wn*64 + (lane>>2);
    int i0 = m0/KANT;
    if (tid < 128){
        iIdx[tid] = (unsigned char)((m0+tid)/KANT - i0);
        sW2[tid] = d_w2p[n0+tid];
    }
    {
        int rr = tid>>6, cc = tid&63;
        int row = min(i0+rr, KSPAN-1);
        *(float2*)(sVi + rr*132 + cc*2) = *(const float2*)(d_Vi + (size_t)row*NPAD + n0 + cc*2);
    }
    float acc[2][8][4];
    #pragma unroll
    for (int a=0;a<2;a++)
        #pragma unroll
        for (int b=0;b<8;b++)
            #pragma unroll
            for (int c=0;c<4;c++) acc[a][b][c]=0.f;
    int r8 = tid>>3, c8 = tid&7;
    auto issue = [&](int k){
        int st = k % 3;
        int k0 = k*64;
        uint32_t sa = smem_u32(sw + st*STG_W) + r8*144 + c8*16;
        #pragma unroll
        for (int it=0; it<4; it++){
            int r = r8 + it*32;
            cpasync16(sa + it*32*144,           d_A2  + (size_t)(m0+r)*KPA + k0 + c8*8);
            cpasync16(sa + 4608*4 + it*32*144,  d_B2t + (size_t)(n0+r)*KPA + k0 + c8*8);
        }
        CommitG();
    };
    issue(0); issue(1);
    const int KT = KPA/64;   // 9
    for (int kt=0; kt<KT; kt++){
        if (kt+2 < KT) WG(1); else WG(0);
        __syncthreads();
        if (kt+2 < KT) issue(kt+2);
        int wb = (kt%3)*STG_W;
        CONSUME_STAGE(wb)
    }
    // epilogue: h = acc + Vi(smem) + Vj[bi[m]] (gather); rs += relu(h)*w2(smem)
    int slot = nt*2 + wn;
    #pragma unroll
    for (int mi=0;mi<2;mi++){
        int rA = wm*32 + mi*16 + (lane>>2), rB = rA+8;
        const float* viA = sVi + iIdx[rA]*132;
        const float* viB = sVi + iIdx[rB]*132;
        int jA = __ldg(d_bi + m0 + rA), jB = __ldg(d_bi + m0 + rB);
        const __nv_bfloat16* vjA = d_Vjb + (size_t)jA*NPAD + n0;
        const __nv_bfloat16* vjB = d_Vjb + (size_t)jB*NPAD + n0;
        float rs0 = 0.f, rs1 = 0.f;
        #pragma unroll
        for (int ni=0;ni<8;ni++){
            int nl = wn*64 + ni*8 + (lane&3)*2;
            float2 wv = *(const float2*)(sW2 + nl);
            float2 va = *(const float2*)(viA + nl);
            float2 vb = *(const float2*)(viB + nl);
            __nv_bfloat162 ja = *(const __nv_bfloat162*)(vjA + nl);
            __nv_bfloat162 jb = *(const __nv_bfloat162*)(vjB + nl);
            float h0 = acc[mi][ni][0] + va.x + __bfloat162float(ja.x);
            float h1 = acc[mi][ni][1] + va.y + __bfloat162float(ja.y);
            rs0 += fmaxf(h0,0.f)*wv.x + fmaxf(h1,0.f)*wv.y;
            float h2 = acc[mi][ni][2] + vb.x + __bfloat162float(jb.x);
            float h3 = acc[mi][ni][3] + vb.y + __bfloat162float(jb.y);
            rs1 += fmaxf(h2,0.f)*wv.x + fmaxf(h3,0.f)*wv.y;
        }
        rs0 += __shfl_xor_sync(0xffffffffu, rs0, 1);
        rs0 += __shfl_xor_sync(0xffffffffu, rs0, 2);
        rs1 += __shfl_xor_sync(0xffffffffu, rs1, 1);
        rs1 += __shfl_xor_sync(0xffffffffu, rs1, 2);
        if ((lane&3)==0){
            d_part[(size_t)slot*MROWS + m0 + rA] = rs0;
            d_part[(size_t)slot*MROWS + m0 + rB] = rs1;
        }
    }
}

__global__ void reduce_sa(){
    int m = blockIdx.x*256 + threadIdx.x;
    if (m >= MROWS) return;
    float s = 0.f;
    #pragma unroll
    for (int t=0; t<NSLOTS; t++) s += d_part[(size_t)t*MROWS + m];
    d_sa[m] = s;
}

// ---------------- refinement ----------------
__global__ void refine_kernel(const float* __restrict__ g, const float* __restrict__ b2){
    int i = blockIdx.x;
    int nv = min(i, KANT);
    __shared__ float p[KANT+1];
    __shared__ int ji[KANT];
    __shared__ float red[128];
    int tid = threadIdx.x;
    float val;
    if (tid==0) val = 0.f;
    else if (tid<=KANT){
        int kk = tid-1;
        val = (kk<nv) ? d_sa[i*KANT+kk] + b2[0] + d_bs[i*KANT+kk] : NEGV;
    } else val = NEGV;
    red[tid]=val; __syncthreads();
    for (int s=64;s>0;s>>=1){ if (tid<s) red[tid]=fmaxf(red[tid],red[tid+s]); __syncthreads(); }
    float mx = red[0]; __syncthreads();
    float e = (tid<=KANT) ? expf(val-mx) : 0.f;
    red[tid]=e; __syncthreads();
    for (int s=64;s>0;s>>=1){ if (tid<s) red[tid]+=red[tid+s]; __syncthreads(); }
    float sum = red[0];
    if (tid<=KANT) p[tid] = e/sum;
    if (tid<KANT) ji[tid] = d_bi[i*KANT+tid];
    __syncthreads();
    for (int d=tid; d<GIDIM; d+=128){
        float a = p[0]*g[(size_t)i*GIDIM+d];
        for (int kk=0;kk<nv;kk++) a += p[kk+1]*g[(size_t)ji[kk]*GIDIM+d];
        d_an[(size_t)i*GIDIM+d] = a;
    }
}

__global__ void build_gateA(const float* __restrict__ g){
    int idx = blockIdx.x*256 + threadIdx.x;
    if (idx >= KSPAN*GIDIM) return;
    int m = idx/GIDIM, d = idx - m*GIDIM;
    d_gateA[(size_t)m*KA + d]         = __float2bfloat16(g[idx]);
    d_gateA[(size_t)m*KA + GIDIM + d] = __float2bfloat16(d_an[idx]);
}

__global__ void final_kernel(const float* __restrict__ b2, float* __restrict__ out){
    int idx = blockIdx.x*256 + threadIdx.x;
    if (idx >= KSPAN*(KANT+1)) return;
    int i = idx/(KANT+1), c = idx - i*(KANT+1);
    float v;
    if (c==0) v = 0.f;
    else {
        int kk = c-1;
        if (i==0) v = (kk==0)? 0.f : NEGV;
        else      v = (kk < min(i,KANT)) ? d_sa[i*KANT+kk] + b2[0] + d_bs[i*KANT+kk] : NEGV;
    }
    out[idx] = v;
}

// ---------------- launch ----------------
extern "C" void kernel_launch(void* const* d_in, const int* in_sizes, int n_in,
                              void* d_out, int out_size){
    const float* g_i     = (const float*)d_in[0];
    const float* mention = (const float*)d_in[1];
    const float* dist_e  = (const float*)d_in[2];
    const float* genre_e = (const float*)d_in[3];
    const float* spk_e   = (const float*)d_in[4];
    const float* coarseW = (const float*)d_in[5];
    const float* W1      = (const float*)d_in[6];
    const float* b1      = (const float*)d_in[7];
    const float* W2      = (const float*)d_in[8];
    const float* b2      = (const float*)d_in[9];
    const float* Wf      = (const float*)d_in[10];
    const float* bfv     = (const float*)d_in[11];
    const int* starts    = (const int*)d_in[12];
    const int* ends      = (const int*)d_in[13];
    const int* gids      = (const int*)d_in[14];
    const int* sids      = (const int*)d_in[15];
    float* out = (float*)d_out;

    cudaFuncSetAttribute(bgemm, cudaFuncAttributeMaxDynamicSharedMemorySize, BG_SMEM);
    cudaFuncSetAttribute(mlp_bf, cudaFuncAttributeMaxDynamicSharedMemorySize, MLP_SMEM);

    prep_master<<<3072,256>>>(0,    g_i, coarseW, W1, Wf, b1, W2, dist_e, genre_e, spk_e); // 1
    prep_master<<<2304,256>>>(3072, g_i, coarseW, W1, Wf, b1, W2, dist_e, genre_e, spk_e); // 2
    prep_master<<<2084,256>>>(5376, g_i, coarseW, W1, Wf, b1, W2, dist_e, genre_e, spk_e); // 3
    bgemm<<<dim3(20, 8),256,BG_SMEM>>>(6, d_gb, nullptr, GIDIM, nullptr, nullptr, gids);   // 4 <- profiled: proj+Vi+Vj
    bgemm<<<dim3(8, 8),256,BG_SMEM>>>(1, d_projb, d_gb, GIDIM, mention, nullptr, nullptr); // 5
    topk_kernel<<<KSPAN,512>>>();                                                          // 6
    build_A<<<MROWS/8,256>>>(0, starts, ends, sids);                                       // 7
    mlp_bf<<<dim3(NPAD/128, MROWS/128),256,MLP_SMEM>>>();                                  // 8
    reduce_sa<<<(MROWS+255)/256,256>>>();
    refine_kernel<<<KSPAN,128>>>(g_i, b2);
    build_gateA<<<(KSPAN*GIDIM+255)/256,256>>>(g_i);
    bgemm<<<dim3(4, 8),256,BG_SMEM>>>(3, d_gateA, d_wft, KA, bfv, g_i, nullptr);
    // iteration 1
    bgemm<<<dim3(16, 8),256,BG_SMEM>>>(7, d_gnb, nullptr, GIDIM, nullptr, nullptr, gids);  // Vi+Vj
    build_A<<<MROWS/8,256>>>(1, starts, ends, sids);
    mlp_bf<<<dim3(NPAD/128, MROWS/128),256,MLP_SMEM>>>();
    reduce_sa<<<(MROWS+255)/256,256>>>();
    final_kernel<<<(KSPAN*(KANT+1)+255)/256,256>>>(b2, out);
}

// round 15
// speedup vs baseline: 2.0498x; 1.0314x over previous
#include <cuda_runtime.h>
#include <cuda_bf16.h>
#include <math.h>
#include <stdint.h>

#define NEGV (-1e10f)
#define KSPAN 1024
#define KANT 50
#define GIDIM 512
#define HID 1000
#define MROWS (KSPAN*KANT)   // 51200
#define KA 1024              // gate GEMM K
#define KPA 576              // MLP K: [gi*gj(512) | onehot18 | pad]
#define NPAD 1024
#define NSLOTS 16

// mlp: 3-stage ring, 64-k chunks
#define STG_W 9216
#define RING_B 110592
#define MLP_SMEM (RING_B + 2112 + 512 + 128)
// sgemm: 2-stage ring, 128-k chunks (stage = (128+128) rows x 68 words)
#define SG_STG_W 17408
#define SG_SMEM (2*SG_STG_W*4)   // 139264

// ---------------- device scratch ----------------
__device__ __nv_bfloat16 d_gb[KSPAN*GIDIM];
__device__ __nv_bfloat16 d_gnb[KSPAN*GIDIM];
__device__ __nv_bfloat16 d_wcb[GIDIM*GIDIM];
__device__ __nv_bfloat16 d_projb[KSPAN*GIDIM];
__device__ float d_ant[KSPAN*KSPAN];
__device__ float d_bs[KSPAN*KANT];
__device__ int   d_bi[KSPAN*KANT];
__device__ __nv_bfloat16 d_A2[(size_t)MROWS*KPA];
__device__ __nv_bfloat16 d_B2t[(size_t)NPAD*KPA];     // [W1c | Vc rows | 0pad]
__device__ __nv_bfloat16 d_B1t[(size_t)NPAD*GIDIM];   // W1a^T
__device__ __nv_bfloat16 d_Bjt[(size_t)NPAD*GIDIM];   // W1b^T
__device__ __nv_bfloat16 d_Vjb[(size_t)KSPAN*NPAD];   // Vj = g@W1b^T (bf16)
__device__ __nv_bfloat16 d_wft[(size_t)GIDIM*KA];
__device__ __nv_bfloat16 d_gateA[(size_t)KSPAN*KA];
__device__ float d_Vi[(size_t)KSPAN*NPAD];
__device__ float d_Vg[8*NPAD];
__device__ float d_w2p[NPAD];
__device__ float d_b1p[NPAD];
__device__ float d_part[(size_t)NSLOTS*MROWS];
__device__ float d_sa[MROWS];
__device__ float d_an[KSPAN*GIDIM];

// ---------------- helpers ----------------
__device__ __forceinline__ uint32_t smem_u32(const void* p){
    uint32_t a; asm("{ .reg .u64 t; cvta.to.shared.u64 t, %1; cvt.u32.u64 %0, t; }" : "=r"(a) : "l"(p));
    return a;
}
__device__ __forceinline__ void cpasync16(uint32_t dst, const void* src){
    asm volatile("cp.async.cg.shared.global [%0], [%1], 16;\n" :: "r"(dst), "l"(src) : "memory");
}
#define WG(n) asm volatile("cp.async.wait_group %0;\n" :: "n"(n) : "memory")
#define CommitG() asm volatile("cp.async.commit_group;\n" ::: "memory")

// ---------------- merged prep (called 3x with base offsets) ----------------
__global__ void prep_master(int base, const float* __restrict__ g, const float* __restrict__ coarseW,
                            const float* __restrict__ W1, const float* __restrict__ Wf,
                            const float* __restrict__ b1, const float* __restrict__ W2,
                            const float* __restrict__ dist_e, const float* __restrict__ genre_e,
                            const float* __restrict__ spk_e){
    int b = base + blockIdx.x, t = threadIdx.x;
    if (b < 2048){
        int i = b*256 + t; d_gb[i] = __float2bfloat16(g[i]);
    } else if (b < 3072){
        int i = (b-2048)*256 + t; d_wcb[i] = __float2bfloat16(coarseW[i]);
    } else if (b < 5120){
        int idx = (b-3072)*256 + t;
        int n = idx >> 9, k = idx & 511;
        float a=0.f, bb=0.f, c=0.f;
        if (n < HID){
            a  = W1[(size_t)k*HID + n];
            bb = W1[(size_t)(512+k)*HID + n];
            c  = W1[(size_t)(1024+k)*HID + n];
        }
        d_B1t[(size_t)n*GIDIM + k] = __float2bfloat16(a);
        d_Bjt[(size_t)n*GIDIM + k] = __float2bfloat16(bb);
        d_B2t[(size_t)n*KPA + k]   = __float2bfloat16(c);
    } else if (b < 5376){
        int idx = (b-5120)*256 + t;
        int n = idx >> 6, c = idx & 63;
        float s = 0.f;
        if (c < 18 && n < HID){
            int bin = c>>1, lab = (c&1)+1;
            for (int k=0;k<20;k++) s += dist_e[bin*20+k]*W1[(size_t)(1536+k)*HID+n]
                                      + spk_e[lab*20+k]*W1[(size_t)(1576+k)*HID+n];
        }
        d_B2t[(size_t)n*KPA + 512 + c] = __float2bfloat16(s);
    } else if (b < 7424){
        int idx = (b-5376)*256 + t;
        int n = idx >> 10, k = idx & 1023;
        d_wft[idx] = __float2bfloat16(Wf[(size_t)k*GIDIM + n]);
    } else if (b < 7428){
        int n = (b-7424)*256 + t;
        d_w2p[n] = (n<HID)? W2[n]:0.f; d_b1p[n] = (n<HID)? b1[n]:0.f;
    } else {
        int idx = (b-7428)*256 + t;
        int row = idx >> 10, n = idx & 1023;
        float s = 0.f;
        if (n < HID)
            for (int k=0;k<20;k++) s += genre_e[row*20+k]*W1[(size_t)(1556+k)*HID+n];
        d_Vg[row*NPAD+n] = s;
    }
}

// ---------------- consume macros ----------------
// 64-k chunk, row stride 36 words (mlp)
#define CONSUME_STAGE(wb)                                                                     \
    _Pragma("unroll")                                                                         \
    for (int ks=0; ks<4; ks++){                                                               \
        unsigned int af[2][4], bfr[8][2];                                                     \
        int aw = ks*8 + (lane&3);                                                             \
        _Pragma("unroll")                                                                     \
        for (int mi=0;mi<2;mi++){                                                             \
            int base = (wb) + (arow+mi*16)*36;                                                \
            af[mi][0]=sw[base+aw]; af[mi][1]=sw[base+288+aw];                                 \
            af[mi][2]=sw[base+aw+4]; af[mi][3]=sw[base+288+aw+4];                             \
        }                                                                                     \
        _Pragma("unroll")                                                                     \
        for (int ni=0;ni<8;ni++){                                                             \
            int base = (wb) + 4608 + (bb0+ni*8)*36 + aw;                                      \
            bfr[ni][0]=sw[base]; bfr[ni][1]=sw[base+4];                                       \
        }                                                                                     \
        _Pragma("unroll")                                                                     \
        for (int mi=0;mi<2;mi++)                                                              \
            _Pragma("unroll")                                                                 \
            for (int ni=0;ni<8;ni++)                                                          \
                asm volatile("mma.sync.aligned.m16n8k16.row.col.f32.bf16.bf16.f32 "           \
                    "{%0,%1,%2,%3},{%4,%5,%6,%7},{%8,%9},{%0,%1,%2,%3};\n"                    \
                    : "+f"(acc[mi][ni][0]), "+f"(acc[mi][ni][1]),                             \
                      "+f"(acc[mi][ni][2]), "+f"(acc[mi][ni][3])                              \
                    : "r"(af[mi][0]), "r"(af[mi][1]), "r"(af[mi][2]), "r"(af[mi][3]),         \
                      "r"(bfr[ni][0]), "r"(bfr[ni][1]));                                      \
    }

// 128-k chunk, row stride 68 words (sgemm)
#define CONSUME_STAGE8(wb)                                                                    \
    _Pragma("unroll")                                                                         \
    for (int ks=0; ks<8; ks++){                                                               \
        unsigned int af[2][4], bfr[8][2];                                                     \
        int aw = ks*8 + (lane&3);                                                             \
        _Pragma("unroll")                                                                     \
        for (int mi=0;mi<2;mi++){                                                             \
            int base = (wb) + (arow+mi*16)*68;                                                \
            af[mi][0]=sw[base+aw]; af[mi][1]=sw[base+544+aw];                                 \
            af[mi][2]=sw[base+aw+4]; af[mi][3]=sw[base+544+aw+4];                             \
        }                                                                                     \
        _Pragma("unroll")                                                                     \
        for (int ni=0;ni<8;ni++){                                                             \
            int base = (wb) + 8704 + (bb0+ni*8)*68 + aw;                                      \
            bfr[ni][0]=sw[base]; bfr[ni][1]=sw[base+4];                                       \
        }                                                                                     \
        _Pragma("unroll")                                                                     \
        for (int mi=0;mi<2;mi++)                                                              \
            _Pragma("unroll")                                                                 \
            for (int ni=0;ni<8;ni++)                                                          \
                asm volatile("mma.sync.aligned.m16n8k16.row.col.f32.bf16.bf16.f32 "           \
                    "{%0,%1,%2,%3},{%4,%5,%6,%7},{%8,%9},{%0,%1,%2,%3};\n"                    \
                    : "+f"(acc[mi][ni][0]), "+f"(acc[mi][ni][1]),                             \
                      "+f"(acc[mi][ni][2]), "+f"(acc[mi][ni][3])                              \
                    : "r"(af[mi][0]), "r"(af[mi][1]), "r"(af[mi][2]), "r"(af[mi][3]),         \
                      "r"(bfr[ni][0]), "r"(bfr[ni][1]));                                      \
    }

// ---------------- small bf16 mma GEMM (128x128), 2-stage/128k/1-barrier ----------------
// modes: 1 ant+mask | 3 gate | 6 iter0: proj(bx<4)+Vi(4..11)+Vj(12..19) | 7 iter1: Vi(bx<8)+Vj(8..15)
__global__ void __launch_bounds__(256) sgemm(int mode, const __nv_bfloat16* __restrict__ A,
        const __nv_bfloat16* __restrict__ B, int Kdim,
        const float* __restrict__ aux0, const float* __restrict__ aux1,
        const int* __restrict__ auxi){
    extern __shared__ char dsm[];
    unsigned int* sw = (unsigned int*)dsm;
    int bx = blockIdx.x;
    const __nv_bfloat16* Bp = B;
    int sel = -1;   // 0 proj, 1 Vi, 2 Vj
    int n0;
    if (mode == 6){
        sel = (bx < 4) ? 0 : (bx < 12 ? 1 : 2);
        Bp = (sel==0) ? d_wcb : (sel==1 ? d_B1t : d_Bjt);
        n0 = ((sel==0) ? bx : (sel==1 ? bx-4 : bx-12))*128;
    } else if (mode == 7){
        sel = (bx < 8) ? 1 : 2;
        Bp = (sel==1) ? d_B1t : d_Bjt;
        n0 = ((sel==1) ? bx : bx-8)*128;
    } else n0 = bx*128;
    int m0 = blockIdx.y*128;
    int tid = threadIdx.x, lane = tid&31, warp = tid>>5;
    int wm = warp&3, wn = warp>>2;
    int arow = wm*32 + (lane>>2);
    int bb0 = wn*64 + (lane>>2);
    float acc[2][8][4];
    #pragma unroll
    for (int a=0;a<2;a++)
        #pragma unroll
        for (int b=0;b<8;b++)
            #pragma unroll
            for (int c=0;c<4;c++) acc[a][b][c]=0.f;
    auto issue = [&](int k){
        int st = k & 1;
        int k0 = k*128;
        uint32_t base = smem_u32(sw + st*SG_STG_W);
        #pragma unroll
        for (int it=0; it<8; it++){
            int seg = tid + it*256;            // 2048 segs: 128 rows x 16
            int row = seg >> 4, col = seg & 15;
            cpasync16(base + row*272 + col*16,           A  + (size_t)(m0+row)*Kdim + k0 + col*8);
            cpasync16(base + 34816 + row*272 + col*16,   Bp + (size_t)(n0+row)*Kdim + k0 + col*8);
        }
        CommitG();
    };
    issue(0);
    int KT = Kdim >> 7;   // 4 (K=512) or 8 (K=1024)
    for (int kt=0; kt<KT; kt++){
        WG(0);
        __syncthreads();
        if (kt+1 < KT) issue(kt+1);
        int wb = (kt&1)*SG_STG_W;
        CONSUME_STAGE8(wb)
    }
    #pragma unroll
    for (int mi=0;mi<2;mi++)
        #pragma unroll
        for (int ni=0;ni<8;ni++)
            #pragma unroll
            for (int q=0;q<4;q++){
                int m = m0 + wm*32 + mi*16 + (lane>>2) + ((q>=2)?8:0);
                int n = n0 + wn*64 + ni*8 + (lane&3)*2 + (q&1);
                float v = acc[mi][ni][q];
                if (sel==0) d_projb[(size_t)m*GIDIM+n] = __float2bfloat16(v);
                else if (sel==1) d_Vi[(size_t)m*NPAD+n] = v + d_b1p[n] + d_Vg[auxi[m]*NPAD+n];
                else if (sel==2) d_Vjb[(size_t)m*NPAD+n] = __float2bfloat16(v);
                else if (mode==1){
                    v += aux0[m] + aux0[n];
                    if (n >= m) v += NEGV;
                    d_ant[(size_t)m*KSPAN+n] = v;
                } else {
                    float f = 1.f/(1.f+expf(-(v+aux0[n])));
                    float gv = aux1[(size_t)m*GIDIM+n];
                    float av = d_an[(size_t)m*GIDIM+n];
                    float o = (m==0)? gv : f*gv + (1.f-f)*av;
                    d_gnb[(size_t)m*GIDIM+n] = __float2bfloat16(o);
                }
            }
}

// ---------------- top-K bitonic ----------------
__global__ void topk_kernel(){
    int row = blockIdx.x;
    __shared__ unsigned long long sk[1024];
    for (int j=threadIdx.x; j<1024; j+=512){
        unsigned int b = __float_as_uint(d_ant[(size_t)row*KSPAN+j]);
        unsigned int asc = (b & 0x80000000u) ? ~b : (b | 0x80000000u);
        sk[j] = (((unsigned long long)(~asc))<<32) | (unsigned int)j;
    }
    __syncthreads();
    for (int k=2;k<=1024;k<<=1)
        for (int j=k>>1;j>0;j>>=1){
            for (int i=threadIdx.x;i<1024;i+=512){
                int ixj = i^j;
                if (ixj>i){
                    bool up = ((i&k)==0);
                    unsigned long long a=sk[i], b=sk[ixj];
                    if ((a>b)==up){ sk[i]=b; sk[ixj]=a; }
                }
            }
            __syncthreads();
        }
    if (threadIdx.x < KANT){
        int j = (int)(sk[threadIdx.x] & 0xffffffffu);
        d_bi[row*KANT+threadIdx.x] = j;
        d_bs[row*KANT+threadIdx.x] = d_ant[(size_t)row*KSPAN+j];
    }
}

// ---------------- build A2 = [gi*gj | onehot18 | 0pad] (576 cols) ----------------
__global__ void build_A(int it, const int* __restrict__ starts, const int* __restrict__ ends,
                        const int* __restrict__ sids){
    const __nv_bfloat16* g = it ? d_gnb : d_gb;
    int warp = threadIdx.x>>5, lane = threadIdx.x&31;
    int r = blockIdx.x*8 + warp;
    int i = r/KANT, j = d_bi[r];
    const uint4* gi4 = (const uint4*)(g + (size_t)i*GIDIM);
    const uint4* gj4 = (const uint4*)(g + (size_t)j*GIDIM);
    uint4 a0 = gi4[lane*2], a1 = gi4[lane*2+1];
    uint4 b0 = gj4[lane*2], b1 = gj4[lane*2+1];
    uint4 p0, p1;
    {
        const __nv_bfloat162* ap = (const __nv_bfloat162*)&a0;
        const __nv_bfloat162* bp = (const __nv_bfloat162*)&b0;
        __nv_bfloat162* pp = (__nv_bfloat162*)&p0;
        #pragma unroll
        for (int w=0; w<4; w++) pp[w] = __hmul2(ap[w], bp[w]);
        ap = (const __nv_bfloat162*)&a1; bp = (const __nv_bfloat162*)&b1;
        pp = (__nv_bfloat162*)&p1;
        #pragma unroll
        for (int w=0; w<4; w++) pp[w] = __hmul2(ap[w], bp[w]);
    }
    __nv_bfloat16* Ar = d_A2 + (size_t)r*KPA;
    ((uint4*)Ar)[lane*2]   = p0;
    ((uint4*)Ar)[lane*2+1] = p1;
    if (lane < 8){
        int d = ends[i]-starts[j];
        int bin = (d>1)+(d>2)+(d>3)+(d>4)+(d>8)+(d>16)+(d>32)+(d>64);
        int lab = (sids[i]==sids[j]) ? 1 : 2;
        int meta = bin*2 + lab - 1;
        uint4 z = make_uint4(0,0,0,0);
        int dd = meta - lane*8;
        if (dd >= 0 && dd < 8){
            unsigned int val = 0x3F80u << (16*(dd&1));
            ((unsigned int*)&z)[dd>>1] = val;
        }
        ((uint4*)(Ar+512))[lane] = z;
    }
}

// ---------------- MLP GEMM (K=576), 3-stage/64k/1-barrier + fused epilogue ----------------
__global__ void __launch_bounds__(256,2) mlp_bf(){
    extern __shared__ char dsm[];
    unsigned int* sw = (unsigned int*)dsm;
    float* sVi = (float*)(dsm + RING_B);
    float* sW2 = (float*)(dsm + RING_B + 2112);
    unsigned char* iIdx = (unsigned char*)(dsm + RING_B + 2624);
    int nt = blockIdx.x, n0 = nt*128, m0 = blockIdx.y*128;
    int tid = threadIdx.x, lane = tid&31, warp = tid>>5;
    int wm = warp&3, wn = warp>>2;
    int arow = wm*32 + (lane>>2);
    int bb0 = wn*64 + (lane>>2);
    int i0 = m0/KANT;
    if (tid < 128){
        iIdx[tid] = (unsigned char)((m0+tid)/KANT - i0);
        sW2[tid] = d_w2p[n0+tid];
    }
    {
        int rr = tid>>6, cc = tid&63;
        int row = min(i0+rr, KSPAN-1);
        *(float2*)(sVi + rr*132 + cc*2) = *(const float2*)(d_Vi + (size_t)row*NPAD + n0 + cc*2);
    }
    float acc[2][8][4];
    #pragma unroll
    for (int a=0;a<2;a++)
        #pragma unroll
        for (int b=0;b<8;b++)
            #pragma unroll
            for (int c=0;c<4;c++) acc[a][b][c]=0.f;
    int r8 = tid>>3, c8 = tid&7;
    auto issue = [&](int k){
        int st = k % 3;
        int k0 = k*64;
        uint32_t sa = smem_u32(sw + st*STG_W) + r8*144 + c8*16;
        #pragma unroll
        for (int it=0; it<4; it++){
            int r = r8 + it*32;
            cpasync16(sa + it*32*144,           d_A2  + (size_t)(m0+r)*KPA + k0 + c8*8);
            cpasync16(sa + 4608*4 + it*32*144,  d_B2t + (size_t)(n0+r)*KPA + k0 + c8*8);
        }
        CommitG();
    };
    issue(0); issue(1);
    const int KT = KPA/64;   // 9
    for (int kt=0; kt<KT; kt++){
        if (kt+2 < KT) WG(1); else WG(0);
        __syncthreads();
        if (kt+2 < KT) issue(kt+2);
        int wb = (kt%3)*STG_W;
        CONSUME_STAGE(wb)
    }
    int slot = nt*2 + wn;
    #pragma unroll
    for (int mi=0;mi<2;mi++){
        int rA = wm*32 + mi*16 + (lane>>2), rB = rA+8;
        const float* viA = sVi + iIdx[rA]*132;
        const float* viB = sVi + iIdx[rB]*132;
        int jA = __ldg(d_bi + m0 + rA), jB = __ldg(d_bi + m0 + rB);
        const __nv_bfloat16* vjA = d_Vjb + (size_t)jA*NPAD + n0;
        const __nv_bfloat16* vjB = d_Vjb + (size_t)jB*NPAD + n0;
        float rs0 = 0.f, rs1 = 0.f;
        #pragma unroll
        for (int ni=0;ni<8;ni++){
            int nl = wn*64 + ni*8 + (lane&3)*2;
            float2 wv = *(const float2*)(sW2 + nl);
            float2 va = *(const float2*)(viA + nl);
            float2 vb = *(const float2*)(viB + nl);
            __nv_bfloat162 ja = *(const __nv_bfloat162*)(vjA + nl);
            __nv_bfloat162 jb = *(const __nv_bfloat162*)(vjB + nl);
            float h0 = acc[mi][ni][0] + va.x + __bfloat162float(ja.x);
            float h1 = acc[mi][ni][1] + va.y + __bfloat162float(ja.y);
            rs0 += fmaxf(h0,0.f)*wv.x + fmaxf(h1,0.f)*wv.y;
            float h2 = acc[mi][ni][2] + vb.x + __bfloat162float(jb.x);
            float h3 = acc[mi][ni][3] + vb.y + __bfloat162float(jb.y);
            rs1 += fmaxf(h2,0.f)*wv.x + fmaxf(h3,0.f)*wv.y;
        }
        rs0 += __shfl_xor_sync(0xffffffffu, rs0, 1);
        rs0 += __shfl_xor_sync(0xffffffffu, rs0, 2);
        rs1 += __shfl_xor_sync(0xffffffffu, rs1, 1);
        rs1 += __shfl_xor_sync(0xffffffffu, rs1, 2);
        if ((lane&3)==0){
            d_part[(size_t)slot*MROWS + m0 + rA] = rs0;
            d_part[(size_t)slot*MROWS + m0 + rB] = rs1;
        }
    }
}

__global__ void reduce_sa(){
    int m = blockIdx.x*256 + threadIdx.x;
    if (m >= MROWS) return;
    float s = 0.f;
    #pragma unroll
    for (int t=0; t<NSLOTS; t++) s += d_part[(size_t)t*MROWS + m];
    d_sa[m] = s;
}

// ---------------- refinement ----------------
__global__ void refine_kernel(const float* __restrict__ g, const float* __restrict__ b2){
    int i = blockIdx.x;
    int nv = min(i, KANT);
    __shared__ float p[KANT+1];
    __shared__ int ji[KANT];
    __shared__ float red[128];
    int tid = threadIdx.x;
    float val;
    if (tid==0) val = 0.f;
    else if (tid<=KANT){
        int kk = tid-1;
        val = (kk<nv) ? d_sa[i*KANT+kk] + b2[0] + d_bs[i*KANT+kk] : NEGV;
    } else val = NEGV;
    red[tid]=val; __syncthreads();
    for (int s=64;s>0;s>>=1){ if (tid<s) red[tid]=fmaxf(red[tid],red[tid+s]); __syncthreads(); }
    float mx = red[0]; __syncthreads();
    float e = (tid<=KANT) ? expf(val-mx) : 0.f;
    red[tid]=e; __syncthreads();
    for (int s=64;s>0;s>>=1){ if (tid<s) red[tid]+=red[tid+s]; __syncthreads(); }
    float sum = red[0];
    if (tid<=KANT) p[tid] = e/sum;
    if (tid<KANT) ji[tid] = d_bi[i*KANT+tid];
    __syncthreads();
    for (int d=tid; d<GIDIM; d+=128){
        float a = p[0]*g[(size_t)i*GIDIM+d];
        for (int kk=0;kk<nv;kk++) a += p[kk+1]*g[(size_t)ji[kk]*GIDIM+d];
        d_an[(size_t)i*GIDIM+d] = a;
    }
}

__global__ void build_gateA(const float* __restrict__ g){
    int idx = blockIdx.x*256 + threadIdx.x;
    if (idx >= KSPAN*GIDIM) return;
    int m = idx/GIDIM, d = idx - m*GIDIM;
    d_gateA[(size_t)m*KA + d]         = __float2bfloat16(g[idx]);
    d_gateA[(size_t)m*KA + GIDIM + d] = __float2bfloat16(d_an[idx]);
}

__global__ void final_kernel(const float* __restrict__ b2, float* __restrict__ out){
    int idx = blockIdx.x*256 + threadIdx.x;
    if (idx >= KSPAN*(KANT+1)) return;
    int i = idx/(KANT+1), c = idx - i*(KANT+1);
    float v;
    if (c==0) v = 0.f;
    else {
        int kk = c-1;
        if (i==0) v = (kk==0)? 0.f : NEGV;
        else      v = (kk < min(i,KANT)) ? d_sa[i*KANT+kk] + b2[0] + d_bs[i*KANT+kk] : NEGV;
    }
    out[idx] = v;
}

// ---------------- launch ----------------
extern "C" void kernel_launch(void* const* d_in, const int* in_sizes, int n_in,
                              void* d_out, int out_size){
    const float* g_i     = (const float*)d_in[0];
    const float* mention = (const float*)d_in[1];
    const float* dist_e  = (const float*)d_in[2];
    const float* genre_e = (const float*)d_in[3];
    const float* spk_e   = (const float*)d_in[4];
    const float* coarseW = (const float*)d_in[5];
    const float* W1      = (const float*)d_in[6];
    const float* b1      = (const float*)d_in[7];
    const float* W2      = (const float*)d_in[8];
    const float* b2      = (const float*)d_in[9];
    const float* Wf      = (const float*)d_in[10];
    const float* bfv     = (const float*)d_in[11];
    const int* starts    = (const int*)d_in[12];
    const int* ends      = (const int*)d_in[13];
    const int* gids      = (const int*)d_in[14];
    const int* sids      = (const int*)d_in[15];
    float* out = (float*)d_out;

    cudaFuncSetAttribute(sgemm, cudaFuncAttributeMaxDynamicSharedMemorySize, SG_SMEM);
    cudaFuncSetAttribute(mlp_bf, cudaFuncAttributeMaxDynamicSharedMemorySize, MLP_SMEM);

    prep_master<<<3072,256>>>(0,    g_i, coarseW, W1, Wf, b1, W2, dist_e, genre_e, spk_e); // 1
    prep_master<<<2304,256>>>(3072, g_i, coarseW, W1, Wf, b1, W2, dist_e, genre_e, spk_e); // 2
    prep_master<<<2084,256>>>(5376, g_i, coarseW, W1, Wf, b1, W2, dist_e, genre_e, spk_e); // 3
    sgemm<<<dim3(20, 8),256,SG_SMEM>>>(6, d_gb, nullptr, GIDIM, nullptr, nullptr, gids);   // 4 <- profiled: proj+Vi+Vj
    sgemm<<<dim3(8, 8),256,SG_SMEM>>>(1, d_projb, d_gb, GIDIM, mention, nullptr, nullptr); // 5
    topk_kernel<<<KSPAN,512>>>();                                                          // 6
    build_A<<<MROWS/8,256>>>(0, starts, ends, sids);                                       // 7
    mlp_bf<<<dim3(NPAD/128, MROWS/128),256,MLP_SMEM>>>();                                  // 8
    reduce_sa<<<(MROWS+255)/256,256>>>();
    refine_kernel<<<KSPAN,128>>>(g_i, b2);
    build_gateA<<<(KSPAN*GIDIM+255)/256,256>>>(g_i);
    sgemm<<<dim3(4, 8),256,SG_SMEM>>>(3, d_gateA, d_wft, KA, bfv, g_i, nullptr);
    // iteration 1
    sgemm<<<dim3(16, 8),256,SG_SMEM>>>(7, d_gnb, nullptr, GIDIM, nullptr, nullptr, gids);  // Vi+Vj
    build_A<<<MROWS/8,256>>>(1, starts, ends, sids);
    mlp_bf<<<dim3(NPAD/128, MROWS/128),256,MLP_SMEM>>>();
    reduce_sa<<<(MROWS+255)/256,256>>>();
    final_kernel<<<(KSPAN*(KANT+1)+255)/256,256>>>(b2, out);
}

// round 16
// speedup vs baseline: 2.1149x; 1.0318x over previous
#include <cuda_runtime.h>
#include <cuda_bf16.h>
#include <math.h>
#include <stdint.h>

#define NEGV (-1e10f)
#define KSPAN 1024
#define KANT 50
#define GIDIM 512
#define HID 1000
#define MROWS (KSPAN*KANT)   // 51200
#define KA 1024              // gate GEMM K
#define KPA 576              // MLP K: [gi*gj(512) | onehot18 | pad] = 6 chunks of 96
#define NPAD 1024
#define NSLOTS 16

// mlp: 2-stage ring, 96-k chunks; stage = A 128x52w + B 128x52w = 13312 words
#define MSTG_W 13312
#define MRING_B 106496
#define MLP_SMEM (MRING_B + 2112 + 512 + 128)   // 109248
// sgemm: 2-stage ring, 128-k chunks
#define SG_STG_W 17408
#define SG_SMEM (2*SG_STG_W*4)   // 139264

// ---------------- device scratch ----------------
__device__ __nv_bfloat16 d_gb[KSPAN*GIDIM];
__device__ __nv_bfloat16 d_gnb[KSPAN*GIDIM];
__device__ __nv_bfloat16 d_wcb[GIDIM*GIDIM];
__device__ __nv_bfloat16 d_projb[KSPAN*GIDIM];
__device__ float d_ant[KSPAN*KSPAN];
__device__ float d_bs[KSPAN*KANT];
__device__ int   d_bi[KSPAN*KANT];
__device__ __nv_bfloat16 d_A2[(size_t)MROWS*KPA];
__device__ __nv_bfloat16 d_B2t[(size_t)NPAD*KPA];     // [W1c | Vc rows | 0pad]
__device__ __nv_bfloat16 d_B1t[(size_t)NPAD*GIDIM];   // W1a^T
__device__ __nv_bfloat16 d_Bjt[(size_t)NPAD*GIDIM];   // W1b^T
__device__ __nv_bfloat16 d_Vjb[(size_t)KSPAN*NPAD];   // Vj = g@W1b^T (bf16)
__device__ __nv_bfloat16 d_wft[(size_t)GIDIM*KA];
__device__ __nv_bfloat16 d_gateA[(size_t)KSPAN*KA];
__device__ float d_Vi[(size_t)KSPAN*NPAD];
__device__ float d_Vg[8*NPAD];
__device__ float d_w2p[NPAD];
__device__ float d_b1p[NPAD];
__device__ float d_part[(size_t)NSLOTS*MROWS];
__device__ float d_sa[MROWS];
__device__ float d_an[KSPAN*GIDIM];

// ---------------- helpers ----------------
__device__ __forceinline__ uint32_t smem_u32(const void* p){
    uint32_t a; asm("{ .reg .u64 t; cvta.to.shared.u64 t, %1; cvt.u32.u64 %0, t; }" : "=r"(a) : "l"(p));
    return a;
}
__device__ __forceinline__ void cpasync16(uint32_t dst, const void* src){
    asm volatile("cp.async.cg.shared.global [%0], [%1], 16;\n" :: "r"(dst), "l"(src) : "memory");
}
#define WG(n) asm volatile("cp.async.wait_group %0;\n" :: "n"(n) : "memory")
#define CommitG() asm volatile("cp.async.commit_group;\n" ::: "memory")

// ---------------- merged prep (called 3x with base offsets) ----------------
__global__ void prep_master(int base, const float* __restrict__ g, const float* __restrict__ coarseW,
                            const float* __restrict__ W1, const float* __restrict__ Wf,
                            const float* __restrict__ b1, const float* __restrict__ W2,
                            const float* __restrict__ dist_e, const float* __restrict__ genre_e,
                            const float* __restrict__ spk_e){
    int b = base + blockIdx.x, t = threadIdx.x;
    if (b < 2048){
        int i = b*256 + t; d_gb[i] = __float2bfloat16(g[i]);
    } else if (b < 3072){
        int i = (b-2048)*256 + t; d_wcb[i] = __float2bfloat16(coarseW[i]);
    } else if (b < 5120){
        int idx = (b-3072)*256 + t;
        int n = idx >> 9, k = idx & 511;
        float a=0.f, bb=0.f, c=0.f;
        if (n < HID){
            a  = W1[(size_t)k*HID + n];
            bb = W1[(size_t)(512+k)*HID + n];
            c  = W1[(size_t)(1024+k)*HID + n];
        }
        d_B1t[(size_t)n*GIDIM + k] = __float2bfloat16(a);
        d_Bjt[(size_t)n*GIDIM + k] = __float2bfloat16(bb);
        d_B2t[(size_t)n*KPA + k]   = __float2bfloat16(c);
    } else if (b < 5376){
        int idx = (b-5120)*256 + t;
        int n = idx >> 6, c = idx & 63;
        float s = 0.f;
        if (c < 18 && n < HID){
            int bin = c>>1, lab = (c&1)+1;
            for (int k=0;k<20;k++) s += dist_e[bin*20+k]*W1[(size_t)(1536+k)*HID+n]
                                      + spk_e[lab*20+k]*W1[(size_t)(1576+k)*HID+n];
        }
        d_B2t[(size_t)n*KPA + 512 + c] = __float2bfloat16(s);
    } else if (b < 7424){
        int idx = (b-5376)*256 + t;
        int n = idx >> 10, k = idx & 1023;
        d_wft[idx] = __float2bfloat16(Wf[(size_t)k*GIDIM + n]);
    } else if (b < 7428){
        int n = (b-7424)*256 + t;
        d_w2p[n] = (n<HID)? W2[n]:0.f; d_b1p[n] = (n<HID)? b1[n]:0.f;
    } else {
        int idx = (b-7428)*256 + t;
        int row = idx >> 10, n = idx & 1023;
        float s = 0.f;
        if (n < HID)
            for (int k=0;k<20;k++) s += genre_e[row*20+k]*W1[(size_t)(1556+k)*HID+n];
        d_Vg[row*NPAD+n] = s;
    }
}

// ---------------- consume macros ----------------
// 96-k chunk, row stride 52 words (mlp)
#define CONSUME_STAGE6(wb)                                                                    \
    _Pragma("unroll")                                                                         \
    for (int ks=0; ks<6; ks++){                                                               \
        unsigned int af[2][4], bfr[8][2];                                                     \
        int aw = ks*8 + (lane&3);                                                             \
        _Pragma("unroll")                                                                     \
        for (int mi=0;mi<2;mi++){                                                             \
            int base = (wb) + (arow+mi*16)*52;                                                \
            af[mi][0]=sw[base+aw]; af[mi][1]=sw[base+416+aw];                                 \
            af[mi][2]=sw[base+aw+4]; af[mi][3]=sw[base+416+aw+4];                             \
        }                                                                                     \
        _Pragma("unroll")                                                                     \
        for (int ni=0;ni<8;ni++){                                                             \
            int base = (wb) + 6656 + (bb0+ni*8)*52 + aw;                                      \
            bfr[ni][0]=sw[base]; bfr[ni][1]=sw[base+4];                                       \
        }                                                                                     \
        _Pragma("unroll")                                                                     \
        for (int mi=0;mi<2;mi++)                                                              \
            _Pragma("unroll")                                                                 \
            for (int ni=0;ni<8;ni++)                                                          \
                asm volatile("mma.sync.aligned.m16n8k16.row.col.f32.bf16.bf16.f32 "           \
                    "{%0,%1,%2,%3},{%4,%5,%6,%7},{%8,%9},{%0,%1,%2,%3};\n"                    \
                    : "+f"(acc[mi][ni][0]), "+f"(acc[mi][ni][1]),                             \
                      "+f"(acc[mi][ni][2]), "+f"(acc[mi][ni][3])                              \
                    : "r"(af[mi][0]), "r"(af[mi][1]), "r"(af[mi][2]), "r"(af[mi][3]),         \
                      "r"(bfr[ni][0]), "r"(bfr[ni][1]));                                      \
    }

// 128-k chunk, row stride 68 words (sgemm)
#define CONSUME_STAGE8(wb)                                                                    \
    _Pragma("unroll")                                                                         \
    for (int ks=0; ks<8; ks++){                                                               \
        unsigned int af[2][4], bfr[8][2];                                                     \
        int aw = ks*8 + (lane&3);                                                             \
        _Pragma("unroll")                                                                     \
        for (int mi=0;mi<2;mi++){                                                             \
            int base = (wb) + (arow+mi*16)*68;                                                \
            af[mi][0]=sw[base+aw]; af[mi][1]=sw[base+544+aw];                                 \
            af[mi][2]=sw[base+aw+4]; af[mi][3]=sw[base+544+aw+4];                             \
        }                                                                                     \
        _Pragma("unroll")                                                                     \
        for (int ni=0;ni<8;ni++){                                                             \
            int base = (wb) + 8704 + (bb0+ni*8)*68 + aw;                                      \
            bfr[ni][0]=sw[base]; bfr[ni][1]=sw[base+4];                                       \
        }                                                                                     \
        _Pragma("unroll")                                                                     \
        for (int mi=0;mi<2;mi++)                                                              \
            _Pragma("unroll")                                                                 \
            for (int ni=0;ni<8;ni++)                                                          \
                asm volatile("mma.sync.aligned.m16n8k16.row.col.f32.bf16.bf16.f32 "           \
                    "{%0,%1,%2,%3},{%4,%5,%6,%7},{%8,%9},{%0,%1,%2,%3};\n"                    \
                    : "+f"(acc[mi][ni][0]), "+f"(acc[mi][ni][1]),                             \
                      "+f"(acc[mi][ni][2]), "+f"(acc[mi][ni][3])                              \
                    : "r"(af[mi][0]), "r"(af[mi][1]), "r"(af[mi][2]), "r"(af[mi][3]),         \
                      "r"(bfr[ni][0]), "r"(bfr[ni][1]));                                      \
    }

// ---------------- small bf16 mma GEMM (128x128), 2-stage/128k ----------------
// modes: 1 ant+mask | 3 gate | 6 iter0: proj(bx<4)+Vi(4..11)+Vj(12..19) | 7 iter1: Vi(bx<8)+Vj(8..15)
__global__ void __launch_bounds__(256) sgemm(int mode, const __nv_bfloat16* __restrict__ A,
        const __nv_bfloat16* __restrict__ B, int Kdim,
        const float* __restrict__ aux0, const float* __restrict__ aux1,
        const int* __restrict__ auxi){
    extern __shared__ char dsm[];
    unsigned int* sw = (unsigned int*)dsm;
    int bx = blockIdx.x;
    const __nv_bfloat16* Bp = B;
    int sel = -1;
    int n0;
    if (mode == 6){
        sel = (bx < 4) ? 0 : (bx < 12 ? 1 : 2);
        Bp = (sel==0) ? d_wcb : (sel==1 ? d_B1t : d_Bjt);
        n0 = ((sel==0) ? bx : (sel==1 ? bx-4 : bx-12))*128;
    } else if (mode == 7){
        sel = (bx < 8) ? 1 : 2;
        Bp = (sel==1) ? d_B1t : d_Bjt;
        n0 = ((sel==1) ? bx : bx-8)*128;
    } else n0 = bx*128;
    int m0 = blockIdx.y*128;
    int tid = threadIdx.x, lane = tid&31, warp = tid>>5;
    int wm = warp&3, wn = warp>>2;
    int arow = wm*32 + (lane>>2);
    int bb0 = wn*64 + (lane>>2);
    float acc[2][8][4];
    #pragma unroll
    for (int a=0;a<2;a++)
        #pragma unroll
        for (int b=0;b<8;b++)
            #pragma unroll
            for (int c=0;c<4;c++) acc[a][b][c]=0.f;
    auto issue = [&](int k){
        int st = k & 1;
        int k0 = k*128;
        uint32_t base = smem_u32(sw + st*SG_STG_W);
        #pragma unroll
        for (int it=0; it<8; it++){
            int seg = tid + it*256;
            int row = seg >> 4, col = seg & 15;
            cpasync16(base + row*272 + col*16,           A  + (size_t)(m0+row)*Kdim + k0 + col*8);
            cpasync16(base + 34816 + row*272 + col*16,   Bp + (size_t)(n0+row)*Kdim + k0 + col*8);
        }
        CommitG();
    };
    issue(0);
    int KT = Kdim >> 7;
    for (int kt=0; kt<KT; kt++){
        WG(0);
        __syncthreads();
        if (kt+1 < KT) issue(kt+1);
        int wb = (kt&1)*SG_STG_W;
        CONSUME_STAGE8(wb)
    }
    #pragma unroll
    for (int mi=0;mi<2;mi++)
        #pragma unroll
        for (int ni=0;ni<8;ni++)
            #pragma unroll
            for (int q=0;q<4;q++){
                int m = m0 + wm*32 + mi*16 + (lane>>2) + ((q>=2)?8:0);
                int n = n0 + wn*64 + ni*8 + (lane&3)*2 + (q&1);
                float v = acc[mi][ni][q];
                if (sel==0) d_projb[(size_t)m*GIDIM+n] = __float2bfloat16(v);
                else if (sel==1) d_Vi[(size_t)m*NPAD+n] = v + d_b1p[n] + d_Vg[auxi[m]*NPAD+n];
                else if (sel==2) d_Vjb[(size_t)m*NPAD+n] = __float2bfloat16(v);
                else if (mode==1){
                    v += aux0[m] + aux0[n];
                    if (n >= m) v += NEGV;
                    d_ant[(size_t)m*KSPAN+n] = v;
                } else {
                    float f = 1.f/(1.f+expf(-(v+aux0[n])));
                    float gv = aux1[(size_t)m*GIDIM+n];
                    float av = d_an[(size_t)m*GIDIM+n];
                    float o = (m==0)? gv : f*gv + (1.f-f)*av;
                    d_gnb[(size_t)m*GIDIM+n] = __float2bfloat16(o);
                }
            }
}

// ---------------- top-K bitonic ----------------
__global__ void topk_kernel(){
    int row = blockIdx.x;
    __shared__ unsigned long long sk[1024];
    for (int j=threadIdx.x; j<1024; j+=512){
        unsigned int b = __float_as_uint(d_ant[(size_t)row*KSPAN+j]);
        unsigned int asc = (b & 0x80000000u) ? ~b : (b | 0x80000000u);
        sk[j] = (((unsigned long long)(~asc))<<32) | (unsigned int)j;
    }
    __syncthreads();
    for (int k=2;k<=1024;k<<=1)
        for (int j=k>>1;j>0;j>>=1){
            for (int i=threadIdx.x;i<1024;i+=512){
                int ixj = i^j;
                if (ixj>i){
                    bool up = ((i&k)==0);
                    unsigned long long a=sk[i], b=sk[ixj];
                    if ((a>b)==up){ sk[i]=b; sk[ixj]=a; }
                }
            }
            __syncthreads();
        }
    if (threadIdx.x < KANT){
        int j = (int)(sk[threadIdx.x] & 0xffffffffu);
        d_bi[row*KANT+threadIdx.x] = j;
        d_bs[row*KANT+threadIdx.x] = d_ant[(size_t)row*KSPAN+j];
    }
}

// ---------------- build A2 = [gi*gj | onehot18 | 0pad] (576 cols) ----------------
__global__ void build_A(int it, const int* __restrict__ starts, const int* __restrict__ ends,
                        const int* __restrict__ sids){
    const __nv_bfloat16* g = it ? d_gnb : d_gb;
    int warp = threadIdx.x>>5, lane = threadIdx.x&31;
    int r = blockIdx.x*8 + warp;
    int i = r/KANT, j = d_bi[r];
    const uint4* gi4 = (const uint4*)(g + (size_t)i*GIDIM);
    const uint4* gj4 = (const uint4*)(g + (size_t)j*GIDIM);
    uint4 a0 = gi4[lane*2], a1 = gi4[lane*2+1];
    uint4 b0 = gj4[lane*2], b1 = gj4[lane*2+1];
    uint4 p0, p1;
    {
        const __nv_bfloat162* ap = (const __nv_bfloat162*)&a0;
        const __nv_bfloat162* bp = (const __nv_bfloat162*)&b0;
        __nv_bfloat162* pp = (__nv_bfloat162*)&p0;
        #pragma unroll
        for (int w=0; w<4; w++) pp[w] = __hmul2(ap[w], bp[w]);
        ap = (const __nv_bfloat162*)&a1; bp = (const __nv_bfloat162*)&b1;
        pp = (__nv_bfloat162*)&p1;
        #pragma unroll
        for (int w=0; w<4; w++) pp[w] = __hmul2(ap[w], bp[w]);
    }
    __nv_bfloat16* Ar = d_A2 + (size_t)r*KPA;
    ((uint4*)Ar)[lane*2]   = p0;
    ((uint4*)Ar)[lane*2+1] = p1;
    if (lane < 8){
        int d = ends[i]-starts[j];
        int bin = (d>1)+(d>2)+(d>3)+(d>4)+(d>8)+(d>16)+(d>32)+(d>64);
        int lab = (sids[i]==sids[j]) ? 1 : 2;
        int meta = bin*2 + lab - 1;
        uint4 z = make_uint4(0,0,0,0);
        int dd = meta - lane*8;
        if (dd >= 0 && dd < 8){
            unsigned int val = 0x3F80u << (16*(dd&1));
            ((unsigned int*)&z)[dd>>1] = val;
        }
        ((uint4*)(Ar+512))[lane] = z;
    }
}

// ---------------- MLP GEMM (K=576), 2-stage/96k/1-barrier + fused epilogue ----------------
__global__ void __launch_bounds__(256,2) mlp_bf(){
    extern __shared__ char dsm[];
    unsigned int* sw = (unsigned int*)dsm;
    float* sVi = (float*)(dsm + MRING_B);
    float* sW2 = (float*)(dsm + MRING_B + 2112);
    unsigned char* iIdx = (unsigned char*)(dsm + MRING_B + 2624);
    int nt = blockIdx.x, n0 = nt*128, m0 = blockIdx.y*128;
    int tid = threadIdx.x, lane = tid&31, warp = tid>>5;
    int wm = warp&3, wn = warp>>2;
    int arow = wm*32 + (lane>>2);
    int bb0 = wn*64 + (lane>>2);
    int i0 = m0/KANT;
    if (tid < 128){
        iIdx[tid] = (unsigned char)((m0+tid)/KANT - i0);
        sW2[tid] = d_w2p[n0+tid];
    }
    {
        int rr = tid>>6, cc = tid&63;
        int row = min(i0+rr, KSPAN-1);
        *(float2*)(sVi + rr*132 + cc*2) = *(const float2*)(d_Vi + (size_t)row*NPAD + n0 + cc*2);
    }
    float acc[2][8][4];
    #pragma unroll
    for (int a=0;a<2;a++)
        #pragma unroll
        for (int b=0;b<8;b++)
            #pragma unroll
            for (int c=0;c<4;c++) acc[a][b][c]=0.f;
    auto issue = [&](int k){
        int st = k & 1;
        int k0 = k*96;
        uint32_t base = smem_u32(sw + st*MSTG_W);
        #pragma unroll
        for (int it=0; it<6; it++){
            int seg = tid + it*256;            // 1536 segs: 128 rows x 12
            int row = seg/12, col = seg - row*12;
            cpasync16(base + row*208 + col*16,          d_A2  + (size_t)(m0+row)*KPA + k0 + col*8);
            cpasync16(base + 26624 + row*208 + col*16,  d_B2t + (size_t)(n0+row)*KPA + k0 + col*8);
        }
        CommitG();
    };
    issue(0);
    const int KT = KPA/96;   // 6
    for (int kt=0; kt<KT; kt++){
        WG(0);
        __syncthreads();
        if (kt+1 < KT) issue(kt+1);
        int wb = (kt&1)*MSTG_W;
        CONSUME_STAGE6(wb)
    }
    int slot = nt*2 + wn;
    #pragma unroll
    for (int mi=0;mi<2;mi++){
        int rA = wm*32 + mi*16 + (lane>>2), rB = rA+8;
        const float* viA = sVi + iIdx[rA]*132;
        const float* viB = sVi + iIdx[rB]*132;
        int jA = __ldg(d_bi + m0 + rA), jB = __ldg(d_bi + m0 + rB);
        const __nv_bfloat16* vjA = d_Vjb + (size_t)jA*NPAD + n0;
        const __nv_bfloat16* vjB = d_Vjb + (size_t)jB*NPAD + n0;
        float rs0 = 0.f, rs1 = 0.f;
        #pragma unroll
        for (int ni=0;ni<8;ni++){
            int nl = wn*64 + ni*8 + (lane&3)*2;
            float2 wv = *(const float2*)(sW2 + nl);
            float2 va = *(const float2*)(viA + nl);
            float2 vb = *(const float2*)(viB + nl);
            __nv_bfloat162 ja = *(const __nv_bfloat162*)(vjA + nl);
            __nv_bfloat162 jb = *(const __nv_bfloat162*)(vjB + nl);
            float h0 = acc[mi][ni][0] + va.x + __bfloat162float(ja.x);
            float h1 = acc[mi][ni][1] + va.y + __bfloat162float(ja.y);
            rs0 += fmaxf(h0,0.f)*wv.x + fmaxf(h1,0.f)*wv.y;
            float h2 = acc[mi][ni][2] + vb.x + __bfloat162float(jb.x);
            float h3 = acc[mi][ni][3] + vb.y + __bfloat162float(jb.y);
            rs1 += fmaxf(h2,0.f)*wv.x + fmaxf(h3,0.f)*wv.y;
        }
        rs0 += __shfl_xor_sync(0xffffffffu, rs0, 1);
        rs0 += __shfl_xor_sync(0xffffffffu, rs0, 2);
        rs1 += __shfl_xor_sync(0xffffffffu, rs1, 1);
        rs1 += __shfl_xor_sync(0xffffffffu, rs1, 2);
        if ((lane&3)==0){
            d_part[(size_t)slot*MROWS + m0 + rA] = rs0;
            d_part[(size_t)slot*MROWS + m0 + rB] = rs1;
        }
    }
}

__global__ void reduce_sa(){
    int m = blockIdx.x*256 + threadIdx.x;
    if (m >= MROWS) return;
    float s = 0.f;
    #pragma unroll
    for (int t=0; t<NSLOTS; t++) s += d_part[(size_t)t*MROWS + m];
    d_sa[m] = s;
}

// ---------------- refinement (+ fused gateA build) ----------------
__global__ void refine_kernel(const float* __restrict__ g, const float* __restrict__ b2){
    int i = blockIdx.x;
    int nv = min(i, KANT);
    __shared__ float p[KANT+1];
    __shared__ int ji[KANT];
    __shared__ float red[128];
    int tid = threadIdx.x;
    float val;
    if (tid==0) val = 0.f;
    else if (tid<=KANT){
        int kk = tid-1;
        val = (kk<nv) ? d_sa[i*KANT+kk] + b2[0] + d_bs[i*KANT+kk] : NEGV;
    } else val = NEGV;
    red[tid]=val; __syncthreads();
    for (int s=64;s>0;s>>=1){ if (tid<s) red[tid]=fmaxf(red[tid],red[tid+s]); __syncthreads(); }
    float mx = red[0]; __syncthreads();
    float e = (tid<=KANT) ? expf(val-mx) : 0.f;
    red[tid]=e; __syncthreads();
    for (int s=64;s>0;s>>=1){ if (tid<s) red[tid]+=red[tid+s]; __syncthreads(); }
    float sum = red[0];
    if (tid<=KANT) p[tid] = e/sum;
    if (tid<KANT) ji[tid] = d_bi[i*KANT+tid];
    __syncthreads();
    for (int d=tid; d<GIDIM; d+=128){
        float gv = g[(size_t)i*GIDIM+d];
        float a = p[0]*gv;
        for (int kk=0;kk<nv;kk++) a += p[kk+1]*g[(size_t)ji[kk]*GIDIM+d];
        d_an[(size_t)i*GIDIM+d] = a;
        d_gateA[(size_t)i*KA + d]         = __float2bfloat16(gv);
        d_gateA[(size_t)i*KA + GIDIM + d] = __float2bfloat16(a);
    }
}

__global__ void final_kernel(const float* __restrict__ b2, float* __restrict__ out){
    int idx = blockIdx.x*256 + threadIdx.x;
    if (idx >= KSPAN*(KANT+1)) return;
    int i = idx/(KANT+1), c = idx - i*(KANT+1);
    float v;
    if (c==0) v = 0.f;
    else {
        int kk = c-1;
        if (i==0) v = (kk==0)? 0.f : NEGV;
        else      v = (kk < min(i,KANT)) ? d_sa[i*KANT+kk] + b2[0] + d_bs[i*KANT+kk] : NEGV;
    }
    out[idx] = v;
}

// ---------------- launch ----------------
extern "C" void kernel_launch(void* const* d_in, const int* in_sizes, int n_in,
                              void* d_out, int out_size){
    const float* g_i     = (const float*)d_in[0];
    const float* mention = (const float*)d_in[1];
    const float* dist_e  = (const float*)d_in[2];
    const float* genre_e = (const float*)d_in[3];
    const float* spk_e   = (const float*)d_in[4];
    const float* coarseW = (const float*)d_in[5];
    const float* W1      = (const float*)d_in[6];
    const float* b1      = (const float*)d_in[7];
    const float* W2      = (const float*)d_in[8];
    const float* b2      = (const float*)d_in[9];
    const float* Wf      = (const float*)d_in[10];
    const float* bfv     = (const float*)d_in[11];
    const int* starts    = (const int*)d_in[12];
    const int* ends      = (const int*)d_in[13];
    const int* gids      = (const int*)d_in[14];
    const int* sids      = (const int*)d_in[15];
    float* out = (float*)d_out;

    cudaFuncSetAttribute(sgemm, cudaFuncAttributeMaxDynamicSharedMemorySize, SG_SMEM);
    cudaFuncSetAttribute(mlp_bf, cudaFuncAttributeMaxDynamicSharedMemorySize, MLP_SMEM);

    prep_master<<<3072,256>>>(0,    g_i, coarseW, W1, Wf, b1, W2, dist_e, genre_e, spk_e);
    prep_master<<<2304,256>>>(3072, g_i, coarseW, W1, Wf, b1, W2, dist_e, genre_e, spk_e);
    prep_master<<<2084,256>>>(5376, g_i, coarseW, W1, Wf, b1, W2, dist_e, genre_e, spk_e);
    sgemm<<<dim3(20, 8),256,SG_SMEM>>>(6, d_gb, nullptr, GIDIM, nullptr, nullptr, gids);   // proj+Vi+Vj
    sgemm<<<dim3(8, 8),256,SG_SMEM>>>(1, d_projb, d_gb, GIDIM, mention, nullptr, nullptr); // ant
    topk_kernel<<<KSPAN,512>>>();
    build_A<<<MROWS/8,256>>>(0, starts, ends, sids);
    mlp_bf<<<dim3(NPAD/128, MROWS/128),256,MLP_SMEM>>>();
    reduce_sa<<<(MROWS+255)/256,256>>>();
    refine_kernel<<<KSPAN,128>>>(g_i, b2);
    sgemm<<<dim3(4, 8),256,SG_SMEM>>>(3, d_gateA, d_wft, KA, bfv, g_i, nullptr);
    // iteration 1
    sgemm<<<dim3(16, 8),256,SG_SMEM>>>(7, d_gnb, nullptr, GIDIM, nullptr, nullptr, gids);  // Vi+Vj
    build_A<<<MROWS/8,256>>>(1, starts, ends, sids);
    mlp_bf<<<dim3(NPAD/128, MROWS/128),256,MLP_SMEM>>>();
    reduce_sa<<<(MROWS+255)/256,256>>>();
    final_kernel<<<(KSPAN*(KANT+1)+255)/256,256>>>(b2, out);
}